// round 1
// baseline (speedup 1.0000x reference)
#include <cuda_runtime.h>
#include <cstdint>
#include <math.h>

#define ALPHA    0.2f
#define NEG_INFV (-1000000000000.0f)
#define LOG2E_F  1.4426950408889634f

#define BATCH 4
#define NN    4096
#define FIN   256
#define FOUT  128

#define BI 64     // query rows per block
#define BJ 128    // key chunk

// scratch (device globals: allocation-free)
__device__ float g_h [BATCH * NN * FOUT];
__device__ float g_s1[BATCH * NN];
__device__ float g_s2[BATCH * NN];

// ---------------------------------------------------------------------------
// Fast 2^x on the FMA/ALU pipe (avoids MUFU.EX2 throughput wall).
// Valid for x <= 0 (softmax guarantees this); clamps at -126.
// Degree-5 poly on f in [-0.5, 0.5]; rel err ~2.4e-6.
// ---------------------------------------------------------------------------
__device__ __forceinline__ float fexp2n(float x) {
    x = fmaxf(x, -126.0f);
    float z = x + 12582912.0f;               // 1.5*2^23: round-to-nearest-int
    int   n = __float_as_int(z) - 0x4B400000;
    float f = x - (z - 12582912.0f);         // f in [-0.5, 0.5]
    float p = fmaf(0.0013333558f, f, 0.0096181291f);
    p = fmaf(p, f, 0.0555041087f);
    p = fmaf(p, f, 0.2402265070f);
    p = fmaf(p, f, 0.6931471806f);
    p = fmaf(p, f, 1.0f);
    return __int_as_float((n + 127) << 23) * p;
}

// ---------------------------------------------------------------------------
// Kernel 1: h = inp @ W   (M=16384, K=256, Nf=128), fp32 tiled GEMM
// block: 128 threads, tile 64x128, 8x8 per thread
// ---------------------------------------------------------------------------
__global__ void __launch_bounds__(128) k_h_gemm(const float* __restrict__ inp,
                                               const float* __restrict__ W) {
    __shared__ float Ws[32][128];
    __shared__ float Is[64][36];

    const int t  = threadIdx.x;
    const int tx = t & 15;
    const int ty = t >> 4;          // 0..7
    const int m0 = blockIdx.x * 64;

    float acc[8][8];
#pragma unroll
    for (int r = 0; r < 8; ++r)
#pragma unroll
        for (int c = 0; c < 8; ++c) acc[r][c] = 0.0f;

    for (int kc = 0; kc < FIN; kc += 32) {
        __syncthreads();
#pragma unroll
        for (int r = 0; r < 8; ++r) {                 // W chunk 32x128
            int v = t + 128 * r;
            int k = v >> 5, fq = v & 31;
            *(float4*)&Ws[k][fq * 4] =
                *(const float4*)&W[(size_t)(kc + k) * FOUT + fq * 4];
        }
#pragma unroll
        for (int r = 0; r < 4; ++r) {                 // inp chunk 64x32
            int v = t + 128 * r;
            int m = v >> 3, kq = v & 7;
            *(float4*)&Is[m][kq * 4] =
                *(const float4*)&inp[(size_t)(m0 + m) * FIN + kc + kq * 4];
        }
        __syncthreads();

#pragma unroll
        for (int k = 0; k < 32; ++k) {
            float iv[8], wv[8];
#pragma unroll
            for (int r = 0; r < 8; ++r) iv[r] = Is[ty * 8 + r][k];
            *(float4*)&wv[0] = *(float4*)&Ws[k][tx * 4];
            *(float4*)&wv[4] = *(float4*)&Ws[k][64 + tx * 4];
#pragma unroll
            for (int r = 0; r < 8; ++r)
#pragma unroll
                for (int c = 0; c < 8; ++c)
                    acc[r][c] = fmaf(iv[r], wv[c], acc[r][c]);
        }
    }

#pragma unroll
    for (int r = 0; r < 8; ++r)
#pragma unroll
        for (int c = 0; c < 8; ++c) {
            int f = (c < 4) ? (tx * 4 + c) : (64 + tx * 4 + (c - 4));
            g_h[(size_t)(m0 + ty * 8 + r) * FOUT + f] = acc[r][c];
        }
}

// ---------------------------------------------------------------------------
// Kernel 1b: s1[r] = h[r,:].a1, s2[r] = h[r,:].a2   (a1 = a[0:128], a2 = a[128:256])
// ---------------------------------------------------------------------------
__global__ void __launch_bounds__(128) k_scores(const float* __restrict__ a) {
    const int row  = blockIdx.x * 4 + (threadIdx.x >> 5);
    const int lane = threadIdx.x & 31;
    const float* hr = g_h + (size_t)row * FOUT;
    float s1 = 0.f, s2 = 0.f;
#pragma unroll
    for (int k = 0; k < 4; ++k) {
        float hv = hr[lane + 32 * k];
        s1 = fmaf(hv, a[lane + 32 * k], s1);
        s2 = fmaf(hv, a[FOUT + lane + 32 * k], s2);
    }
#pragma unroll
    for (int off = 16; off; off >>= 1) {
        s1 += __shfl_xor_sync(0xffffffffu, s1, off);
        s2 += __shfl_xor_sync(0xffffffffu, s2, off);
    }
    if (lane == 0) { g_s1[row] = s1; g_s2[row] = s2; }
}

// ---------------------------------------------------------------------------
// Kernel 2: fused masked-softmax attention + (attention @ h) + ELU
// grid (N/BI, B), block 128 threads. Online softmax, flash-style tiling.
// ---------------------------------------------------------------------------
struct AttnSmem {
    float hs[BJ][FOUT];   // 64 KB  : h chunk [j][f]
    float Pt[BJ][68];     // 34.8KB : exp'd probs transposed [j][i] (pad 68)
    float s2s[BJ];
    float m[BI], l[BI], sc[BI], s1s[BI];
};

__global__ void __launch_bounds__(128) k_attn(const float* __restrict__ adj,
                                              float* __restrict__ out) {
    extern __shared__ char smem_raw[];
    AttnSmem* s = reinterpret_cast<AttnSmem*>(smem_raw);

    const int b    = blockIdx.y;
    const int i0   = blockIdx.x * BI;
    const int t    = threadIdx.x;
    const int lane = t & 31;
    const int w    = t >> 5;        // warp 0..3
    const int tx   = t & 15;
    const int ty   = t >> 4;        // 0..7

    if (t < BI) {
        s->m[t]   = -3.0e38f;
        s->l[t]   = 0.0f;
        s->s1s[t] = g_s1[(size_t)b * NN + i0 + t];
    }

    float acc[8][8];
#pragma unroll
    for (int r = 0; r < 8; ++r)
#pragma unroll
        for (int c = 0; c < 8; ++c) acc[r][c] = 0.0f;

    const float* hbase = g_h + (size_t)b * NN * FOUT;

    for (int jc = 0; jc < NN; jc += BJ) {
        __syncthreads();   // protect hs/Pt from previous chunk's GEMM readers

        // stage h chunk [128][128] (coalesced float4)
#pragma unroll
        for (int r = 0; r < 32; ++r) {
            int v = t + 128 * r;
            int j = v >> 5, fq = v & 31;
            *(float4*)&s->hs[j][fq * 4] =
                *(const float4*)&hbase[(size_t)(jc + j) * FOUT + fq * 4];
        }
        s->s2s[t] = g_s2[(size_t)b * NN + jc + t];
        __syncthreads();

        // ---- logit + online-softmax phase: warp w owns local rows w*16..w*16+15
        for (int rr = 0; rr < 16; ++rr) {
            const int i = w * 16 + rr;
            const float* arow = adj + ((size_t)b * NN + i0 + i) * NN + jc;
            const float s1v = s->s1s[i];
            float raw[4];
            float mx = -3.0e38f;
#pragma unroll
            for (int k = 0; k < 4; ++k) {
                int   j  = lane + 32 * k;
                float av = arow[j];
                float e  = s1v + s->s2s[j];
                float lr = (e > 0.0f) ? e : ALPHA * e;
                raw[k]   = (av > 0.0f) ? av * lr : NEG_INFV;
                mx = fmaxf(mx, raw[k]);
            }
#pragma unroll
            for (int off = 16; off; off >>= 1)
                mx = fmaxf(mx, __shfl_xor_sync(0xffffffffu, mx, off));

            const float mold = s->m[i];
            const float mnew = fmaxf(mold, mx);
            float sum = 0.0f;
#pragma unroll
            for (int k = 0; k < 4; ++k) {
                float p = fexp2n((raw[k] - mnew) * LOG2E_F);
                s->Pt[lane + 32 * k][i] = p;
                sum += p;
            }
#pragma unroll
            for (int off = 16; off; off >>= 1)
                sum += __shfl_xor_sync(0xffffffffu, sum, off);

            if (lane == 0) {
                float scale = fexp2n((mold - mnew) * LOG2E_F);
                s->l[i]  = s->l[i] * scale + sum;
                s->m[i]  = mnew;
                s->sc[i] = scale;
            }
        }
        __syncthreads();

        // ---- rescale accumulators by this chunk's max-correction
        float scl[8];
#pragma unroll
        for (int r = 0; r < 8; ++r) scl[r] = s->sc[ty * 8 + r];
#pragma unroll
        for (int r = 0; r < 8; ++r)
#pragma unroll
            for (int c = 0; c < 8; ++c) acc[r][c] *= scl[r];

        // ---- accumulate: acc += P^T-chunk @ h-chunk  (64x128x128 fp32)
#pragma unroll 8
        for (int j = 0; j < BJ; ++j) {
            float pv[8], hv[8];
            *(float4*)&pv[0] = *(float4*)&s->Pt[j][ty * 8];
            *(float4*)&pv[4] = *(float4*)&s->Pt[j][ty * 8 + 4];
            *(float4*)&hv[0] = *(float4*)&s->hs[j][tx * 4];
            *(float4*)&hv[4] = *(float4*)&s->hs[j][64 + tx * 4];
#pragma unroll
            for (int r = 0; r < 8; ++r)
#pragma unroll
                for (int c = 0; c < 8; ++c)
                    acc[r][c] = fmaf(pv[r], hv[c], acc[r][c]);
        }
    }

    // ---- epilogue: normalize, ELU, write
    float linv[8];
#pragma unroll
    for (int r = 0; r < 8; ++r) linv[r] = 1.0f / s->l[ty * 8 + r];

#pragma unroll
    for (int r = 0; r < 8; ++r) {
        const int i = ty * 8 + r;
#pragma unroll
        for (int c = 0; c < 8; ++c) {
            int   f = (c < 4) ? (tx * 4 + c) : (64 + tx * 4 + (c - 4));
            float v = acc[r][c] * linv[r];
            v = (v > 0.0f) ? v : expm1f(v);
            out[((size_t)b * NN + i0 + i) * FOUT + f] = v;
        }
    }
}

// ---------------------------------------------------------------------------
extern "C" void kernel_launch(void* const* d_in, const int* in_sizes, int n_in,
                              void* d_out, int out_size) {
    const float* inp = (const float*)d_in[0];   // (4,4096,256)
    const float* adj = (const float*)d_in[1];   // (4,4096,4096)
    const float* W   = (const float*)d_in[2];   // (256,128)
    const float* a   = (const float*)d_in[3];   // (256,1)
    float* out = (float*)d_out;                 // (4,4096,128)

    (void)in_sizes; (void)n_in; (void)out_size;

    const int smem_bytes = (int)sizeof(AttnSmem);   // ~101.9 KB
    cudaFuncSetAttribute(k_attn, cudaFuncAttributeMaxDynamicSharedMemorySize,
                         smem_bytes);

    k_h_gemm<<<(BATCH * NN) / 64, 128>>>(inp, W);
    k_scores<<<(BATCH * NN) / 4, 128>>>(a);

    dim3 grid(NN / BI, BATCH);
    k_attn<<<grid, 128, smem_bytes>>>(adj, out);
}

// round 2
// speedup vs baseline: 1.0109x; 1.0109x over previous
#include <cuda_runtime.h>
#include <cstdint>
#include <math.h>

#define ALPHA    0.2f
#define NEG_INFV (-1000000000000.0f)
#define LOG2E_F  1.4426950408889634f

#define BATCH 4
#define NN    4096
#define FIN   256
#define FOUT  128

#define BI 64     // query rows per block
#define BJ 128    // key chunk

typedef unsigned long long u64;

// scratch (device globals: allocation-free)
__device__ float g_h [BATCH * NN * FOUT];
__device__ float g_s1[BATCH * NN];
__device__ float g_s2[BATCH * NN];

// ---------------------------------------------------------------------------
// Packed fp32x2 helpers (sm_103a FFMA2 path — ptxas never emits it from C++)
// ---------------------------------------------------------------------------
__device__ __forceinline__ void ffma2(u64& d, u64 a, u64 b) {
    asm("fma.rn.f32x2 %0, %1, %2, %0;" : "+l"(d) : "l"(a), "l"(b));
}
__device__ __forceinline__ u64 mul2(u64 a, u64 b) {
    u64 d; asm("mul.rn.f32x2 %0, %1, %2;" : "=l"(d) : "l"(a), "l"(b)); return d;
}
__device__ __forceinline__ u64 bcast2(float x) {
    u64 r; asm("mov.b64 %0, {%1, %1};" : "=l"(r) : "f"(x)); return r;
}
__device__ __forceinline__ float2 unpack2(u64 v) {
    float2 f; asm("mov.b64 {%0, %1}, %2;" : "=f"(f.x), "=f"(f.y) : "l"(v)); return f;
}

// ---------------------------------------------------------------------------
// Fast 2^x on the FMA/ALU pipe (avoids MUFU.EX2 throughput wall).
// Valid for x <= 0 (softmax guarantees this); clamps at -126.
// ---------------------------------------------------------------------------
__device__ __forceinline__ float fexp2n(float x) {
    x = fmaxf(x, -126.0f);
    float z = x + 12582912.0f;               // 1.5*2^23: round-to-nearest-int
    int   n = __float_as_int(z) - 0x4B400000;
    float f = x - (z - 12582912.0f);         // f in [-0.5, 0.5]
    float p = fmaf(0.0013333558f, f, 0.0096181291f);
    p = fmaf(p, f, 0.0555041087f);
    p = fmaf(p, f, 0.2402265070f);
    p = fmaf(p, f, 0.6931471806f);
    p = fmaf(p, f, 1.0f);
    return __int_as_float((n + 127) << 23) * p;
}

// ---------------------------------------------------------------------------
// Kernel 1: h = inp @ W   (M=16384, K=256, Nf=128), fp32x2 tiled GEMM
// ---------------------------------------------------------------------------
__global__ void __launch_bounds__(128) k_h_gemm(const float* __restrict__ inp,
                                               const float* __restrict__ W) {
    __shared__ float Ws[32][128];
    __shared__ float Is[64][36];

    const int t  = threadIdx.x;
    const int tx = t & 15;
    const int ty = t >> 4;          // 0..7
    const int m0 = blockIdx.x * 64;

    u64 acc2[8][4];
#pragma unroll
    for (int r = 0; r < 8; ++r)
#pragma unroll
        for (int c = 0; c < 4; ++c) acc2[r][c] = 0ull;

    for (int kc = 0; kc < FIN; kc += 32) {
        __syncthreads();
#pragma unroll
        for (int r = 0; r < 8; ++r) {                 // W chunk 32x128
            int v = t + 128 * r;
            int k = v >> 5, fq = v & 31;
            *(float4*)&Ws[k][fq * 4] =
                *(const float4*)&W[(size_t)(kc + k) * FOUT + fq * 4];
        }
#pragma unroll
        for (int r = 0; r < 4; ++r) {                 // inp chunk 64x32
            int v = t + 128 * r;
            int m = v >> 3, kq = v & 7;
            *(float4*)&Is[m][kq * 4] =
                *(const float4*)&inp[(size_t)(m0 + m) * FIN + kc + kq * 4];
        }
        __syncthreads();

#pragma unroll
        for (int k = 0; k < 32; ++k) {
            u64 wv2[4];
            {
                ulonglong2 w01 = *(const ulonglong2*)&Ws[k][tx * 4];
                ulonglong2 w23 = *(const ulonglong2*)&Ws[k][64 + tx * 4];
                wv2[0] = w01.x; wv2[1] = w01.y; wv2[2] = w23.x; wv2[3] = w23.y;
            }
            u64 iv2[8];
#pragma unroll
            for (int r = 0; r < 8; ++r) iv2[r] = bcast2(Is[ty * 8 + r][k]);
#pragma unroll
            for (int r = 0; r < 8; ++r)
#pragma unroll
                for (int c = 0; c < 4; ++c)
                    ffma2(acc2[r][c], iv2[r], wv2[c]);
        }
    }

#pragma unroll
    for (int r = 0; r < 8; ++r)
#pragma unroll
        for (int c = 0; c < 4; ++c) {
            int f = (c < 2) ? (tx * 4 + 2 * c) : (64 + tx * 4 + 2 * (c - 2));
            float2 v = unpack2(acc2[r][c]);
            g_h[(size_t)(m0 + ty * 8 + r) * FOUT + f]     = v.x;
            g_h[(size_t)(m0 + ty * 8 + r) * FOUT + f + 1] = v.y;
        }
}

// ---------------------------------------------------------------------------
// Kernel 1b: s1[r] = h[r,:].a1, s2[r] = h[r,:].a2
// ---------------------------------------------------------------------------
__global__ void __launch_bounds__(128) k_scores(const float* __restrict__ a) {
    const int row  = blockIdx.x * 4 + (threadIdx.x >> 5);
    const int lane = threadIdx.x & 31;
    const float* hr = g_h + (size_t)row * FOUT;
    float s1 = 0.f, s2 = 0.f;
#pragma unroll
    for (int k = 0; k < 4; ++k) {
        float hv = hr[lane + 32 * k];
        s1 = fmaf(hv, a[lane + 32 * k], s1);
        s2 = fmaf(hv, a[FOUT + lane + 32 * k], s2);
    }
#pragma unroll
    for (int off = 16; off; off >>= 1) {
        s1 += __shfl_xor_sync(0xffffffffu, s1, off);
        s2 += __shfl_xor_sync(0xffffffffu, s2, off);
    }
    if (lane == 0) { g_s1[row] = s1; g_s2[row] = s2; }
}

// ---------------------------------------------------------------------------
// Kernel 2: fused masked-softmax attention + (attention @ h) + ELU
// grid (N/BI, B), block 128 threads, 2 CTAs/SM. Online softmax, flash-style.
// P kept untransposed: stores are conflict-free (lanes span j), GEMM reads
// are broadcast LDS (conflict-free by definition).
// ---------------------------------------------------------------------------
struct AttnSmem {
    float hs[BJ][FOUT];   // 64 KB : h chunk [j][f]
    float P [BI][BJ];     // 32 KB : exp'd probs [i][j]
    float s2s[BJ];
    float m[BI], l[BI], sc[BI], s1s[BI];
};

__global__ void __launch_bounds__(128, 2) k_attn(const float* __restrict__ adj,
                                                 float* __restrict__ out) {
    extern __shared__ char smem_raw[];
    AttnSmem* s = reinterpret_cast<AttnSmem*>(smem_raw);

    const int b    = blockIdx.y;
    const int i0   = blockIdx.x * BI;
    const int t    = threadIdx.x;
    const int lane = t & 31;
    const int w    = t >> 5;        // warp 0..3
    const int tx   = t & 15;
    const int ty   = t >> 4;        // 0..7

    if (t < BI) {
        s->m[t]   = -3.0e38f;
        s->l[t]   = 0.0f;
        s->s1s[t] = g_s1[(size_t)b * NN + i0 + t];
    }

    u64 acc2[8][4];
#pragma unroll
    for (int r = 0; r < 8; ++r)
#pragma unroll
        for (int c = 0; c < 4; ++c) acc2[r][c] = 0ull;

    const float* hbase = g_h + (size_t)b * NN * FOUT;

    for (int jc = 0; jc < NN; jc += BJ) {
        __syncthreads();   // protect hs/P from previous chunk's GEMM readers

        // stage h chunk [128][128] (coalesced float4)
#pragma unroll
        for (int r = 0; r < 32; ++r) {
            int v = t + 128 * r;
            int j = v >> 5, fq = v & 31;
            *(float4*)&s->hs[j][fq * 4] =
                *(const float4*)&hbase[(size_t)(jc + j) * FOUT + fq * 4];
        }
        s->s2s[t] = g_s2[(size_t)b * NN + jc + t];
        __syncthreads();

        // ---- logit + online-softmax phase: warp w owns local rows w*16..+15
        for (int rr = 0; rr < 16; ++rr) {
            const int i = w * 16 + rr;
            const float* arow = adj + ((size_t)b * NN + i0 + i) * NN + jc;
            const float s1v = s->s1s[i];
            float raw[4];
            float mx = -3.0e38f;
#pragma unroll
            for (int k = 0; k < 4; ++k) {
                int   j  = lane + 32 * k;
                float av = arow[j];
                float e  = s1v + s->s2s[j];
                float lr = (e > 0.0f) ? e : ALPHA * e;
                raw[k]   = (av > 0.0f) ? av * lr : NEG_INFV;
                mx = fmaxf(mx, raw[k]);
            }
#pragma unroll
            for (int off = 16; off; off >>= 1)
                mx = fmaxf(mx, __shfl_xor_sync(0xffffffffu, mx, off));

            const float mold = s->m[i];
            const float mnew = fmaxf(mold, mx);
            float sum = 0.0f;
#pragma unroll
            for (int k = 0; k < 4; ++k) {
                float p = fexp2n((raw[k] - mnew) * LOG2E_F);
                s->P[i][lane + 32 * k] = p;       // conflict-free STS
                sum += p;
            }
#pragma unroll
            for (int off = 16; off; off >>= 1)
                sum += __shfl_xor_sync(0xffffffffu, sum, off);

            if (lane == 0) {
                float scale = fexp2n((mold - mnew) * LOG2E_F);
                s->l[i]  = s->l[i] * scale + sum;
                s->m[i]  = mnew;
                s->sc[i] = scale;
            }
        }
        __syncthreads();

        // ---- rescale accumulators by this chunk's max-correction
#pragma unroll
        for (int r = 0; r < 8; ++r) {
            u64 scl2 = bcast2(s->sc[ty * 8 + r]);
#pragma unroll
            for (int c = 0; c < 4; ++c) acc2[r][c] = mul2(acc2[r][c], scl2);
        }

        // ---- accumulate: acc += P-chunk @ h-chunk  (64x128x128, fp32x2)
#pragma unroll 4
        for (int j = 0; j < BJ; ++j) {
            u64 hv2[4];
            {
                ulonglong2 h01 = *(const ulonglong2*)&s->hs[j][tx * 4];
                ulonglong2 h23 = *(const ulonglong2*)&s->hs[j][64 + tx * 4];
                hv2[0] = h01.x; hv2[1] = h01.y; hv2[2] = h23.x; hv2[3] = h23.y;
            }
            u64 pv2[8];
#pragma unroll
            for (int r = 0; r < 8; ++r) pv2[r] = bcast2(s->P[ty * 8 + r][j]);
#pragma unroll
            for (int r = 0; r < 8; ++r)
#pragma unroll
                for (int c = 0; c < 4; ++c)
                    ffma2(acc2[r][c], pv2[r], hv2[c]);
        }
    }

    // ---- epilogue: normalize, ELU, write
    float linv[8];
#pragma unroll
    for (int r = 0; r < 8; ++r) linv[r] = 1.0f / s->l[ty * 8 + r];

#pragma unroll
    for (int r = 0; r < 8; ++r) {
        const int i = ty * 8 + r;
#pragma unroll
        for (int c = 0; c < 4; ++c) {
            int    f = (c < 2) ? (tx * 4 + 2 * c) : (64 + tx * 4 + 2 * (c - 2));
            float2 v = unpack2(acc2[r][c]);
            float v0 = v.x * linv[r];
            float v1 = v.y * linv[r];
            v0 = (v0 > 0.0f) ? v0 : expm1f(v0);
            v1 = (v1 > 0.0f) ? v1 : expm1f(v1);
            out[((size_t)b * NN + i0 + i) * FOUT + f]     = v0;
            out[((size_t)b * NN + i0 + i) * FOUT + f + 1] = v1;
        }
    }
}

// ---------------------------------------------------------------------------
extern "C" void kernel_launch(void* const* d_in, const int* in_sizes, int n_in,
                              void* d_out, int out_size) {
    const float* inp = (const float*)d_in[0];   // (4,4096,256)
    const float* adj = (const float*)d_in[1];   // (4,4096,4096)
    const float* W   = (const float*)d_in[2];   // (256,128)
    const float* a   = (const float*)d_in[3];   // (256,1)
    float* out = (float*)d_out;                 // (4,4096,128)

    (void)in_sizes; (void)n_in; (void)out_size;

    const int smem_bytes = (int)sizeof(AttnSmem);   // ~97.8 KB -> 2 CTAs/SM
    cudaFuncSetAttribute(k_attn, cudaFuncAttributeMaxDynamicSharedMemorySize,
                         smem_bytes);

    k_h_gemm<<<(BATCH * NN) / 64, 128>>>(inp, W);
    k_scores<<<(BATCH * NN) / 4, 128>>>(a);

    dim3 grid(NN / BI, BATCH);
    k_attn<<<grid, 128, smem_bytes>>>(adj, out);
}

// round 3
// speedup vs baseline: 1.2912x; 1.2772x over previous
#include <cuda_runtime.h>
#include <cstdint>
#include <math.h>

#define ALPHA    0.2f
#define NEG_INFV (-1000000000000.0f)
#define LOG2E_F  1.4426950408889634f

#define BATCH 4
#define NN    4096
#define FIN   256
#define FOUT  128

#define BI 64     // query rows per block
#define BJ 128    // key chunk

typedef unsigned long long u64;

// scratch (device globals: allocation-free)
__device__ float    g_h [BATCH * NN * FOUT];
__device__ float    g_s1[BATCH * NN];
__device__ float    g_s2[BATCH * NN];
__device__ unsigned g_s2max_enc[BATCH];

// ---------------------------------------------------------------------------
// order-preserving float<->uint encoding (for atomicMax on floats)
// ---------------------------------------------------------------------------
__device__ __forceinline__ unsigned enc_f(float f) {
    int i = __float_as_int(f);
    unsigned u = (unsigned)i;
    return (i < 0) ? ~u : (u | 0x80000000u);
}
__device__ __forceinline__ float dec_f(unsigned u) {
    int i = (u & 0x80000000u) ? (int)(u & 0x7fffffffu) : (int)~u;
    return __int_as_float(i);
}

// ---------------------------------------------------------------------------
// Packed fp32x2 helpers (sm_103a FFMA2 path — ptxas never emits it from C++)
// ---------------------------------------------------------------------------
__device__ __forceinline__ void ffma2(u64& d, u64 a, u64 b) {
    asm("fma.rn.f32x2 %0, %1, %2, %0;" : "+l"(d) : "l"(a), "l"(b));
}
__device__ __forceinline__ u64 bcast2(float x) {
    u64 r; asm("mov.b64 %0, {%1, %1};" : "=l"(r) : "f"(x)); return r;
}
__device__ __forceinline__ float2 unpack2(u64 v) {
    float2 f; asm("mov.b64 {%0, %1}, %2;" : "=f"(f.x), "=f"(f.y) : "l"(v)); return f;
}

// ---------------------------------------------------------------------------
// Fast 2^x on the FMA/ALU pipe (avoids MUFU.EX2 throughput wall). x <= 0.
// ---------------------------------------------------------------------------
__device__ __forceinline__ float fexp2n(float x) {
    x = fmaxf(x, -126.0f);
    float z = x + 12582912.0f;               // 1.5*2^23: round-to-nearest-int
    int   n = __float_as_int(z) - 0x4B400000;
    float f = x - (z - 12582912.0f);         // f in [-0.5, 0.5]
    float p = fmaf(0.0013333558f, f, 0.0096181291f);
    p = fmaf(p, f, 0.0555041087f);
    p = fmaf(p, f, 0.2402265070f);
    p = fmaf(p, f, 0.6931471806f);
    p = fmaf(p, f, 1.0f);
    return __int_as_float((n + 127) << 23) * p;
}

// ---------------------------------------------------------------------------
// Kernel 1: h = inp @ W   (M=16384, K=256, Nf=128), fp32x2 tiled GEMM
// Also initializes g_s2max_enc (runs before k_scores in-stream).
// ---------------------------------------------------------------------------
__global__ void __launch_bounds__(128) k_h_gemm(const float* __restrict__ inp,
                                               const float* __restrict__ W) {
    if (blockIdx.x == 0 && threadIdx.x < BATCH) g_s2max_enc[threadIdx.x] = 0u;

    __shared__ float Ws[32][128];
    __shared__ float Is[64][36];

    const int t  = threadIdx.x;
    const int tx = t & 15;
    const int ty = t >> 4;          // 0..7
    const int m0 = blockIdx.x * 64;

    u64 acc2[8][4];
#pragma unroll
    for (int r = 0; r < 8; ++r)
#pragma unroll
        for (int c = 0; c < 4; ++c) acc2[r][c] = 0ull;

    for (int kc = 0; kc < FIN; kc += 32) {
        __syncthreads();
#pragma unroll
        for (int r = 0; r < 8; ++r) {                 // W chunk 32x128
            int v = t + 128 * r;
            int k = v >> 5, fq = v & 31;
            *(float4*)&Ws[k][fq * 4] =
                *(const float4*)&W[(size_t)(kc + k) * FOUT + fq * 4];
        }
#pragma unroll
        for (int r = 0; r < 4; ++r) {                 // inp chunk 64x32
            int v = t + 128 * r;
            int m = v >> 3, kq = v & 7;
            *(float4*)&Is[m][kq * 4] =
                *(const float4*)&inp[(size_t)(m0 + m) * FIN + kc + kq * 4];
        }
        __syncthreads();

#pragma unroll
        for (int k = 0; k < 32; ++k) {
            u64 wv2[4];
            {
                ulonglong2 w01 = *(const ulonglong2*)&Ws[k][tx * 4];
                ulonglong2 w23 = *(const ulonglong2*)&Ws[k][64 + tx * 4];
                wv2[0] = w01.x; wv2[1] = w01.y; wv2[2] = w23.x; wv2[3] = w23.y;
            }
            u64 iv2[8];
#pragma unroll
            for (int r = 0; r < 8; ++r) iv2[r] = bcast2(Is[ty * 8 + r][k]);
#pragma unroll
            for (int r = 0; r < 8; ++r)
#pragma unroll
                for (int c = 0; c < 4; ++c)
                    ffma2(acc2[r][c], iv2[r], wv2[c]);
        }
    }

#pragma unroll
    for (int r = 0; r < 8; ++r)
#pragma unroll
        for (int c = 0; c < 4; ++c) {
            int f = (c < 2) ? (tx * 4 + 2 * c) : (64 + tx * 4 + 2 * (c - 2));
            float2 v = unpack2(acc2[r][c]);
            g_h[(size_t)(m0 + ty * 8 + r) * FOUT + f]     = v.x;
            g_h[(size_t)(m0 + ty * 8 + r) * FOUT + f + 1] = v.y;
        }
}

// ---------------------------------------------------------------------------
// Kernel 1b: s1[r], s2[r]; also batch-wise max of s2 via encoded atomicMax
// ---------------------------------------------------------------------------
__global__ void __launch_bounds__(128) k_scores(const float* __restrict__ a) {
    const int row  = blockIdx.x * 4 + (threadIdx.x >> 5);
    const int lane = threadIdx.x & 31;
    const float* hr = g_h + (size_t)row * FOUT;
    float s1 = 0.f, s2 = 0.f;
#pragma unroll
    for (int k = 0; k < 4; ++k) {
        float hv = hr[lane + 32 * k];
        s1 = fmaf(hv, a[lane + 32 * k], s1);
        s2 = fmaf(hv, a[FOUT + lane + 32 * k], s2);
    }
#pragma unroll
    for (int off = 16; off; off >>= 1) {
        s1 += __shfl_xor_sync(0xffffffffu, s1, off);
        s2 += __shfl_xor_sync(0xffffffffu, s2, off);
    }
    if (lane == 0) {
        g_s1[row] = s1;
        g_s2[row] = s2;
        atomicMax(&g_s2max_enc[row / NN], enc_f(s2));
    }
}

// ---------------------------------------------------------------------------
// Kernel 2: masked-softmax attention + (attention @ h) + ELU.
// NO online softmax: per-row static shift M_i = max(0, s1_i + max_j s2_j)
// (a valid upper bound since adj<=1) makes the logit phase pure streaming
// and defers the softmax denominator to a single end-of-kernel reduction.
// ---------------------------------------------------------------------------
struct AttnSmem {
    float hs[BJ][FOUT];   // 64 KB : h chunk [j][f]
    float P [BI][BJ];     // 32 KB : exp'd (unnormalized) probs [i][j]
    float s2s[BJ];
    float base[BI];       // -M_i * LOG2E
    float l[BI];          // final row sums
};

__global__ void __launch_bounds__(128, 2) k_attn(const float* __restrict__ adj,
                                                 float* __restrict__ out) {
    extern __shared__ char smem_raw[];
    AttnSmem* s = reinterpret_cast<AttnSmem*>(smem_raw);

    const int b    = blockIdx.y;
    const int i0   = blockIdx.x * BI;
    const int t    = threadIdx.x;
    const int lane = t & 31;
    const int w    = t >> 5;        // warp 0..3
    const int tx   = t & 15;
    const int ty   = t >> 4;        // 0..7

    if (t < BI) {
        float s2max = dec_f(g_s2max_enc[b]);
        float s1v   = g_s1[(size_t)b * NN + i0 + t];
        float M     = fmaxf(0.0f, s1v + s2max);
        s->base[t]  = -M * LOG2E_F;
    }

    u64 acc2[8][4];
#pragma unroll
    for (int r = 0; r < 8; ++r)
#pragma unroll
        for (int c = 0; c < 4; ++c) acc2[r][c] = 0ull;

    float rowsum[16];
#pragma unroll
    for (int r = 0; r < 16; ++r) rowsum[r] = 0.0f;

    const float* hbase = g_h + (size_t)b * NN * FOUT;

    for (int jc = 0; jc < NN; jc += BJ) {
        __syncthreads();   // protect hs/P from previous chunk's readers

        // stage h chunk [128][128] (coalesced float4)
#pragma unroll
        for (int r = 0; r < 32; ++r) {
            int v = t + 128 * r;
            int j = v >> 5, fq = v & 31;
            *(float4*)&s->hs[j][fq * 4] =
                *(const float4*)&hbase[(size_t)(jc + j) * FOUT + fq * 4];
        }
        s->s2s[t] = g_s2[(size_t)b * NN + jc + t];
        __syncthreads();

        // ---- streaming logit phase: warp w owns rows w*16..+15,
        //      lane owns j = lane*4..lane*4+3 (LDG.128 / STS.128)
#pragma unroll 2
        for (int rr = 0; rr < 16; ++rr) {
            const int i = w * 16 + rr;
            const float* arow = adj + ((size_t)b * NN + i0 + i) * NN + jc;
            const float4 av  = *(const float4*)&arow[lane * 4];
            const float4 s2v = *(const float4*)&s->s2s[lane * 4];
            const float  bs  = s->base[i];
            const float  s1v = 0.0f;  // folded into base? no: need s1 here
            (void)s1v;
            // e = lrelu(s1 + s2). s1 is folded into base? No — base only
            // holds the shift. Recover s1 from base is impossible; use smem.
            float p0, p1, p2, p3;
            {
                // s1 needed separately: read from g_s1 once per row via
                // broadcast through base trick is not possible; use s->l as
                // temporary? Simpler: s1 stored in s->P row? Use shfl-free
                // direct global broadcast (L1-cached, once per row).
                float s1r = __ldg(&g_s1[(size_t)b * NN + i0 + i]);
                float e0 = s1r + s2v.x, e1 = s1r + s2v.y;
                float e2 = s1r + s2v.z, e3 = s1r + s2v.w;
                float l0 = fmaxf(e0, ALPHA * e0), l1 = fmaxf(e1, ALPHA * e1);
                float l2 = fmaxf(e2, ALPHA * e2), l3 = fmaxf(e3, ALPHA * e3);
                float r0 = (av.x > 0.0f) ? av.x * l0 : NEG_INFV;
                float r1 = (av.y > 0.0f) ? av.y * l1 : NEG_INFV;
                float r2 = (av.z > 0.0f) ? av.z * l2 : NEG_INFV;
                float r3 = (av.w > 0.0f) ? av.w * l3 : NEG_INFV;
                p0 = fexp2n(fmaf(r0, LOG2E_F, bs));
                p1 = fexp2n(fmaf(r1, LOG2E_F, bs));
                p2 = fexp2n(fmaf(r2, LOG2E_F, bs));
                p3 = fexp2n(fmaf(r3, LOG2E_F, bs));
                p0 = (av.x > 0.0f) ? p0 : 0.0f;
                p1 = (av.y > 0.0f) ? p1 : 0.0f;
                p2 = (av.z > 0.0f) ? p2 : 0.0f;
                p3 = (av.w > 0.0f) ? p3 : 0.0f;
            }
            *(float4*)&s->P[i][lane * 4] = make_float4(p0, p1, p2, p3);
            rowsum[rr] += (p0 + p1) + (p2 + p3);
        }
        __syncthreads();

        // ---- accumulate: acc += P-chunk @ h-chunk  (64x128x128, fp32x2)
#pragma unroll 4
        for (int j = 0; j < BJ; ++j) {
            u64 hv2[4];
            {
                ulonglong2 h01 = *(const ulonglong2*)&s->hs[j][tx * 4];
                ulonglong2 h23 = *(const ulonglong2*)&s->hs[j][64 + tx * 4];
                hv2[0] = h01.x; hv2[1] = h01.y; hv2[2] = h23.x; hv2[3] = h23.y;
            }
            u64 pv2[8];
#pragma unroll
            for (int r = 0; r < 8; ++r) pv2[r] = bcast2(s->P[ty * 8 + r][j]);
#pragma unroll
            for (int r = 0; r < 8; ++r)
#pragma unroll
                for (int c = 0; c < 4; ++c)
                    ffma2(acc2[r][c], pv2[r], hv2[c]);
        }
    }

    // ---- final row-sum reduction (once for the whole kernel)
#pragma unroll
    for (int rr = 0; rr < 16; ++rr) {
        float v = rowsum[rr];
#pragma unroll
        for (int off = 16; off; off >>= 1)
            v += __shfl_xor_sync(0xffffffffu, v, off);
        if (lane == 0) s->l[w * 16 + rr] = v;
    }
    __syncthreads();

    // ---- epilogue: normalize, ELU, write
    float linv[8];
#pragma unroll
    for (int r = 0; r < 8; ++r) linv[r] = 1.0f / s->l[ty * 8 + r];

#pragma unroll
    for (int r = 0; r < 8; ++r) {
        const int i = ty * 8 + r;
#pragma unroll
        for (int c = 0; c < 4; ++c) {
            int    f = (c < 2) ? (tx * 4 + 2 * c) : (64 + tx * 4 + 2 * (c - 2));
            float2 v = unpack2(acc2[r][c]);
            float v0 = v.x * linv[r];
            float v1 = v.y * linv[r];
            v0 = (v0 > 0.0f) ? v0 : expm1f(v0);
            v1 = (v1 > 0.0f) ? v1 : expm1f(v1);
            out[((size_t)b * NN + i0 + i) * FOUT + f]     = v0;
            out[((size_t)b * NN + i0 + i) * FOUT + f + 1] = v1;
        }
    }
}

// ---------------------------------------------------------------------------
extern "C" void kernel_launch(void* const* d_in, const int* in_sizes, int n_in,
                              void* d_out, int out_size) {
    const float* inp = (const float*)d_in[0];   // (4,4096,256)
    const float* adj = (const float*)d_in[1];   // (4,4096,4096)
    const float* W   = (const float*)d_in[2];   // (256,128)
    const float* a   = (const float*)d_in[3];   // (256,1)
    float* out = (float*)d_out;                 // (4,4096,128)

    (void)in_sizes; (void)n_in; (void)out_size;

    const int smem_bytes = (int)sizeof(AttnSmem);   // ~96.8 KB -> 2 CTAs/SM
    cudaFuncSetAttribute(k_attn, cudaFuncAttributeMaxDynamicSharedMemorySize,
                         smem_bytes);

    k_h_gemm<<<(BATCH * NN) / 64, 128>>>(inp, W);
    k_scores<<<(BATCH * NN) / 4, 128>>>(a);

    dim3 grid(NN / BI, BATCH);
    k_attn<<<grid, 128, smem_bytes>>>(adj, out);
}

// round 5
// speedup vs baseline: 1.5442x; 1.1960x over previous
#include <cuda_runtime.h>
#include <cstdint>
#include <math.h>

#define ALPHA    0.2f
#define NEG_INFV (-1000000000000.0f)
#define LOG2E_F  1.4426950408889634f

#define BATCH 4
#define NN    4096
#define FIN   256
#define FOUT  128

#define BI 64              // query rows per block
#define BJ 64              // key chunk
#define NCHUNK (NN / BJ)   // 64

typedef unsigned long long u64;
typedef unsigned int       u32;

// scratch (device globals: allocation-free)
__device__ float    g_h [BATCH * NN * FOUT];
__device__ float    g_s1[BATCH * NN];
__device__ float    g_s2[BATCH * NN];
__device__ unsigned g_s2max_enc[BATCH];

// ---------------------------------------------------------------------------
// helpers
// ---------------------------------------------------------------------------
__device__ __forceinline__ unsigned enc_f(float f) {
    int i = __float_as_int(f);
    unsigned u = (unsigned)i;
    return (i < 0) ? ~u : (u | 0x80000000u);
}
__device__ __forceinline__ float dec_f(unsigned u) {
    int i = (u & 0x80000000u) ? (int)(u & 0x7fffffffu) : (int)~u;
    return __int_as_float(i);
}
__device__ __forceinline__ void ffma2(u64& d, u64 a, u64 b) {
    asm("fma.rn.f32x2 %0, %1, %2, %0;" : "+l"(d) : "l"(a), "l"(b));
}
__device__ __forceinline__ u64 bcast2(float x) {
    u64 r; asm("mov.b64 %0, {%1, %1};" : "=l"(r) : "f"(x)); return r;
}
__device__ __forceinline__ float2 unpack2(u64 v) {
    float2 f; asm("mov.b64 {%0, %1}, %2;" : "=f"(f.x), "=f"(f.y) : "l"(v)); return f;
}
__device__ __forceinline__ float fexp2n(float x) {   // 2^x, x <= 0, FMA-pipe only
    x = fmaxf(x, -126.0f);
    float z = x + 12582912.0f;
    int   n = __float_as_int(z) - 0x4B400000;
    float f = x - (z - 12582912.0f);
    float p = fmaf(0.0013333558f, f, 0.0096181291f);
    p = fmaf(p, f, 0.0555041087f);
    p = fmaf(p, f, 0.2402265070f);
    p = fmaf(p, f, 0.6931471806f);
    p = fmaf(p, f, 1.0f);
    return __int_as_float((n + 127) << 23) * p;
}
__device__ __forceinline__ u32 smem_u32(const void* p) {
    u32 a;
    asm("{ .reg .u64 t; cvta.to.shared.u64 t, %1; cvt.u32.u64 %0, t; }"
        : "=r"(a) : "l"(p));
    return a;
}
__device__ __forceinline__ void cp16(u32 dst, const void* src) {
    asm volatile("cp.async.cg.shared.global [%0], [%1], 16;"
                 :: "r"(dst), "l"(src) : "memory");
}
__device__ __forceinline__ void cp4(u32 dst, const void* src) {
    asm volatile("cp.async.ca.shared.global [%0], [%1], 4;"
                 :: "r"(dst), "l"(src) : "memory");
}
#define CP_COMMIT() asm volatile("cp.async.commit_group;" ::: "memory")
#define CP_WAIT0()  asm volatile("cp.async.wait_group 0;"  ::: "memory")

// ---------------------------------------------------------------------------
// Kernel 1: h = inp @ W   (fp32x2 tiled GEMM), also inits s2max
// ---------------------------------------------------------------------------
__global__ void __launch_bounds__(128) k_h_gemm(const float* __restrict__ inp,
                                               const float* __restrict__ W) {
    if (blockIdx.x == 0 && threadIdx.x < BATCH) g_s2max_enc[threadIdx.x] = 0u;

    __shared__ float Ws[32][128];
    __shared__ float Is[64][36];

    const int t  = threadIdx.x;
    const int tx = t & 15;
    const int ty = t >> 4;
    const int m0 = blockIdx.x * 64;

    u64 acc2[8][4];
#pragma unroll
    for (int r = 0; r < 8; ++r)
#pragma unroll
        for (int c = 0; c < 4; ++c) acc2[r][c] = 0ull;

    for (int kc = 0; kc < FIN; kc += 32) {
        __syncthreads();
#pragma unroll
        for (int r = 0; r < 8; ++r) {
            int v = t + 128 * r;
            int k = v >> 5, fq = v & 31;
            *(float4*)&Ws[k][fq * 4] =
                *(const float4*)&W[(size_t)(kc + k) * FOUT + fq * 4];
        }
#pragma unroll
        for (int r = 0; r < 4; ++r) {
            int v = t + 128 * r;
            int m = v >> 3, kq = v & 7;
            *(float4*)&Is[m][kq * 4] =
                *(const float4*)&inp[(size_t)(m0 + m) * FIN + kc + kq * 4];
        }
        __syncthreads();

#pragma unroll
        for (int k = 0; k < 32; ++k) {
            u64 wv2[4];
            {
                ulonglong2 w01 = *(const ulonglong2*)&Ws[k][tx * 4];
                ulonglong2 w23 = *(const ulonglong2*)&Ws[k][64 + tx * 4];
                wv2[0] = w01.x; wv2[1] = w01.y; wv2[2] = w23.x; wv2[3] = w23.y;
            }
            u64 iv2[8];
#pragma unroll
            for (int r = 0; r < 8; ++r) iv2[r] = bcast2(Is[ty * 8 + r][k]);
#pragma unroll
            for (int r = 0; r < 8; ++r)
#pragma unroll
                for (int c = 0; c < 4; ++c)
                    ffma2(acc2[r][c], iv2[r], wv2[c]);
        }
    }

#pragma unroll
    for (int r = 0; r < 8; ++r)
#pragma unroll
        for (int c = 0; c < 4; ++c) {
            int f = (c < 2) ? (tx * 4 + 2 * c) : (64 + tx * 4 + 2 * (c - 2));
            float2 v = unpack2(acc2[r][c]);
            g_h[(size_t)(m0 + ty * 8 + r) * FOUT + f]     = v.x;
            g_h[(size_t)(m0 + ty * 8 + r) * FOUT + f + 1] = v.y;
        }
}

// ---------------------------------------------------------------------------
// Kernel 1b: s1, s2, batchwise max(s2)
// ---------------------------------------------------------------------------
__global__ void __launch_bounds__(128) k_scores(const float* __restrict__ a) {
    const int row  = blockIdx.x * 4 + (threadIdx.x >> 5);
    const int lane = threadIdx.x & 31;
    const float* hr = g_h + (size_t)row * FOUT;
    float s1 = 0.f, s2 = 0.f;
#pragma unroll
    for (int k = 0; k < 4; ++k) {
        float hv = hr[lane + 32 * k];
        s1 = fmaf(hv, a[lane + 32 * k], s1);
        s2 = fmaf(hv, a[FOUT + lane + 32 * k], s2);
    }
#pragma unroll
    for (int off = 16; off; off >>= 1) {
        s1 += __shfl_xor_sync(0xffffffffu, s1, off);
        s2 += __shfl_xor_sync(0xffffffffu, s2, off);
    }
    if (lane == 0) {
        g_s1[row] = s1;
        g_s2[row] = s2;
        atomicMax(&g_s2max_enc[row / NN], enc_f(s2));
    }
}

// ---------------------------------------------------------------------------
// Kernel 2: static-shift masked softmax + P@h (FFMA2) + ELU.
// Fixes vs R3: cp.async double-buffered adj (latency hidden under GEMM),
// fully-unrolled logit loop (no local-mem reg arrays), P padded to 66 floats
// (dual-broadcast, conflict-free GEMM reads).
// ---------------------------------------------------------------------------
struct AttnSmem {
    float hs[BJ][FOUT];        // 32 KB : h chunk [j][f]
    float P [BI][66];          // 16.5KB: probs, padded rows (bank-conflict-free)
    float adjb[2][BI][BJ];     // 32 KB : double-buffered adj tile
    float s2s[2][BJ];
    float l[BI];
};

__global__ void __launch_bounds__(128, 2) k_attn(const float* __restrict__ adj,
                                                 float* __restrict__ out) {
    extern __shared__ char smc[];
    AttnSmem& s = *reinterpret_cast<AttnSmem*>(smc);

    const int b    = blockIdx.y;
    const int i0   = blockIdx.x * BI;
    const int t    = threadIdx.x;
    const int lane = t & 31;
    const int w    = t >> 5;        // warp 0..3
    const int tx   = t & 15;
    const int ty   = t >> 4;        // 0..7

    const float s2max = dec_f(g_s2max_enc[b]);
    float s1r[16], bsr[16], rowsum[16];
#pragma unroll
    for (int rr = 0; rr < 16; ++rr) {
        float v = g_s1[(size_t)b * NN + i0 + w * 16 + rr];
        s1r[rr]    = v;
        bsr[rr]    = -fmaxf(0.0f, v + s2max) * LOG2E_F;
        rowsum[rr] = 0.0f;
    }

    u64 acc2[8][4];
#pragma unroll
    for (int r = 0; r < 8; ++r)
#pragma unroll
        for (int c = 0; c < 4; ++c) acc2[r][c] = 0ull;

    const float* hbase = g_h + (size_t)b * NN * FOUT;
    const float* arow0 = adj + ((size_t)b * NN + i0) * NN;

    // ---- prologue: prefetch chunk 0 (adj tile + s2 slice)
    {
#pragma unroll
        for (int r = 0; r < 8; ++r) {
            int v = t + 128 * r;
            int row = v >> 4, q = v & 15;
            cp16(smem_u32(&s.adjb[0][row][q * 4]), arow0 + (size_t)row * NN + q * 4);
        }
        if (t < BJ) cp4(smem_u32(&s.s2s[0][t]), &g_s2[(size_t)b * NN + t]);
        CP_COMMIT();
    }

    for (int c = 0; c < NCHUNK; ++c) {
        const int jc  = c * BJ;
        const int buf = c & 1;

        __syncthreads();            // previous GEMM done with hs/P

        // ---- stage h chunk [64][128] from L2 (coalesced float4)
#pragma unroll
        for (int r = 0; r < 16; ++r) {
            int v = t + 128 * r;
            int j = v >> 5, fq = v & 31;
            *(float4*)&s.hs[j][fq * 4] =
                *(const float4*)&hbase[(size_t)(jc + j) * FOUT + fq * 4];
        }
        CP_WAIT0();                 // adj chunk c landed
        __syncthreads();

        // ---- streaming logit phase (fully unrolled; adj from smem)
#pragma unroll
        for (int rr = 0; rr < 16; ++rr) {
            const int i = w * 16 + rr;
            const float2 av  = *(const float2*)&s.adjb[buf][i][lane * 2];
            const float2 s2v = *(const float2*)&s.s2s[buf][lane * 2];
            const float  s1v = s1r[rr];
            const float  bs  = bsr[rr];

            float e0 = s1v + s2v.x,          e1 = s1v + s2v.y;
            float l0 = fmaxf(e0, ALPHA * e0), l1 = fmaxf(e1, ALPHA * e1);
            float r0 = (av.x > 0.0f) ? av.x * l0 : NEG_INFV;
            float r1 = (av.y > 0.0f) ? av.y * l1 : NEG_INFV;
            float p0 = fexp2n(fmaf(r0, LOG2E_F, bs));
            float p1 = fexp2n(fmaf(r1, LOG2E_F, bs));
            p0 = (av.x > 0.0f) ? p0 : 0.0f;
            p1 = (av.y > 0.0f) ? p1 : 0.0f;

            rowsum[rr] += p0 + p1;
            *(float2*)&s.P[i][lane * 2] = make_float2(p0, p1);
        }
        __syncthreads();

        // ---- prefetch chunk c+1 (overlaps with GEMM below)
        if (c + 1 < NCHUNK) {
            const int nb = buf ^ 1;
            const float* asrc = arow0 + jc + BJ;
#pragma unroll
            for (int r = 0; r < 8; ++r) {
                int v = t + 128 * r;
                int row = v >> 4, q = v & 15;
                cp16(smem_u32(&s.adjb[nb][row][q * 4]), asrc + (size_t)row * NN + q * 4);
            }
            if (t < BJ) cp4(smem_u32(&s.s2s[nb][t]),
                            &g_s2[(size_t)b * NN + jc + BJ + t]);
            CP_COMMIT();
        }

        // ---- accumulate: acc += P-chunk @ h-chunk  (64x64x128, fp32x2)
#pragma unroll 8
        for (int j = 0; j < BJ; ++j) {
            u64 hv2[4];
            {
                ulonglong2 h01 = *(const ulonglong2*)&s.hs[j][tx * 4];
                ulonglong2 h23 = *(const ulonglong2*)&s.hs[j][64 + tx * 4];
                hv2[0] = h01.x; hv2[1] = h01.y; hv2[2] = h23.x; hv2[3] = h23.y;
            }
            u64 pv2[8];
#pragma unroll
            for (int r = 0; r < 8; ++r) pv2[r] = bcast2(s.P[ty * 8 + r][j]);
#pragma unroll
            for (int r = 0; r < 8; ++r)
#pragma unroll
                for (int cc = 0; cc < 4; ++cc)
                    ffma2(acc2[r][cc], pv2[r], hv2[cc]);
        }
    }

    // ---- final row-sum reduction (once for the whole kernel)
#pragma unroll
    for (int rr = 0; rr < 16; ++rr) {
        float v = rowsum[rr];
#pragma unroll
        for (int off = 16; off; off >>= 1)
            v += __shfl_xor_sync(0xffffffffu, v, off);
        if (lane == 0) s.l[w * 16 + rr] = v;
    }
    __syncthreads();

    // ---- epilogue: normalize, ELU, write
    float linv[8];
#pragma unroll
    for (int r = 0; r < 8; ++r) linv[r] = 1.0f / s.l[ty * 8 + r];

#pragma unroll
    for (int r = 0; r < 8; ++r) {
        const int i = ty * 8 + r;
#pragma unroll
        for (int c = 0; c < 4; ++c) {
            int    f = (c < 2) ? (tx * 4 + 2 * c) : (64 + tx * 4 + 2 * (c - 2));
            float2 v = unpack2(acc2[r][c]);
            float v0 = v.x * linv[r];
            float v1 = v.y * linv[r];
            v0 = (v0 > 0.0f) ? v0 : expm1f(v0);
            v1 = (v1 > 0.0f) ? v1 : expm1f(v1);
            out[((size_t)b * NN + i0 + i) * FOUT + f]     = v0;
            out[((size_t)b * NN + i0 + i) * FOUT + f + 1] = v1;
        }
    }
}

// ---------------------------------------------------------------------------
extern "C" void kernel_launch(void* const* d_in, const int* in_sizes, int n_in,
                              void* d_out, int out_size) {
    const float* inp = (const float*)d_in[0];   // (4,4096,256)
    const float* adj = (const float*)d_in[1];   // (4,4096,4096)
    const float* W   = (const float*)d_in[2];   // (256,128)
    const float* a   = (const float*)d_in[3];   // (256,1)
    float* out = (float*)d_out;                 // (4,4096,128)

    (void)in_sizes; (void)n_in; (void)out_size;

    const int smem_bytes = (int)sizeof(AttnSmem);   // ~83 KB -> 2 CTAs/SM
    cudaFuncSetAttribute(k_attn, cudaFuncAttributeMaxDynamicSharedMemorySize,
                         smem_bytes);

    k_h_gemm<<<(BATCH * NN) / 64, 128>>>(inp, W);
    k_scores<<<(BATCH * NN) / 4, 128>>>(a);

    dim3 grid(NN / BI, BATCH);
    k_attn<<<grid, 128, smem_bytes>>>(adj, out);
}

// round 6
// speedup vs baseline: 2.7599x; 1.7873x over previous
#include <cuda_runtime.h>
#include <cuda_bf16.h>
#include <cstdint>
#include <math.h>

#define ALPHA    0.2f
#define NEG_INFV (-1000000000000.0f)
#define LOG2E_F  1.4426950408889634f

#define BATCH 4
#define NN    4096
#define FIN   256
#define FOUT  128

#define BI 64              // query rows per block
#define BJ 64              // key chunk
#define NCHUNK (NN / BJ)   // 64

#define PH_STRIDE 72       // bf16 per P row (144 B, 16B-aligned, bank step 4)
#define HH_STRIDE 136      // bf16 per h row (272 B, 16B-aligned, bank step 4)

typedef unsigned long long u64;
typedef unsigned int       u32;

// scratch (device globals: allocation-free)
__device__ float          g_h   [BATCH * NN * FOUT];
__device__ __nv_bfloat16  g_h_hi[BATCH * NN * FOUT];
__device__ __nv_bfloat16  g_h_lo[BATCH * NN * FOUT];
__device__ float          g_s1[BATCH * NN];
__device__ float          g_s2[BATCH * NN];
__device__ unsigned       g_s2max_enc[BATCH];

// ---------------------------------------------------------------------------
// helpers
// ---------------------------------------------------------------------------
__device__ __forceinline__ unsigned enc_f(float f) {
    int i = __float_as_int(f);
    unsigned u = (unsigned)i;
    return (i < 0) ? ~u : (u | 0x80000000u);
}
__device__ __forceinline__ float dec_f(unsigned u) {
    int i = (u & 0x80000000u) ? (int)(u & 0x7fffffffu) : (int)~u;
    return __int_as_float(i);
}
__device__ __forceinline__ void ffma2(u64& d, u64 a, u64 b) {
    asm("fma.rn.f32x2 %0, %1, %2, %0;" : "+l"(d) : "l"(a), "l"(b));
}
__device__ __forceinline__ u64 bcast2(float x) {
    u64 r; asm("mov.b64 %0, {%1, %1};" : "=l"(r) : "f"(x)); return r;
}
__device__ __forceinline__ float2 unpack2(u64 v) {
    float2 f; asm("mov.b64 {%0, %1}, %2;" : "=f"(f.x), "=f"(f.y) : "l"(v)); return f;
}
__device__ __forceinline__ float fexp2n(float x) {   // 2^x, x <= 0, FMA-pipe only
    x = fmaxf(x, -126.0f);
    float z = x + 12582912.0f;
    int   n = __float_as_int(z) - 0x4B400000;
    float f = x - (z - 12582912.0f);
    float p = fmaf(0.0013333558f, f, 0.0096181291f);
    p = fmaf(p, f, 0.0555041087f);
    p = fmaf(p, f, 0.2402265070f);
    p = fmaf(p, f, 0.6931471806f);
    p = fmaf(p, f, 1.0f);
    return __int_as_float((n + 127) << 23) * p;
}
__device__ __forceinline__ u32 smem_u32(const void* p) {
    u32 a;
    asm("{ .reg .u64 t; cvta.to.shared.u64 t, %1; cvt.u32.u64 %0, t; }"
        : "=r"(a) : "l"(p));
    return a;
}
__device__ __forceinline__ void cp16(u32 dst, const void* src) {
    asm volatile("cp.async.cg.shared.global [%0], [%1], 16;"
                 :: "r"(dst), "l"(src) : "memory");
}
__device__ __forceinline__ void cp4(u32 dst, const void* src) {
    asm volatile("cp.async.ca.shared.global [%0], [%1], 4;"
                 :: "r"(dst), "l"(src) : "memory");
}
#define CP_COMMIT() asm volatile("cp.async.commit_group;" ::: "memory")
#define CP_WAIT1()  asm volatile("cp.async.wait_group 1;"  ::: "memory")

__device__ __forceinline__ void ldsm_x4(u32& r0, u32& r1, u32& r2, u32& r3, u32 a) {
    asm volatile("ldmatrix.sync.aligned.m8n8.x4.shared.b16 {%0,%1,%2,%3}, [%4];"
                 : "=r"(r0), "=r"(r1), "=r"(r2), "=r"(r3) : "r"(a));
}
__device__ __forceinline__ void ldsm_x4t(u32& r0, u32& r1, u32& r2, u32& r3, u32 a) {
    asm volatile("ldmatrix.sync.aligned.m8n8.x4.trans.shared.b16 {%0,%1,%2,%3}, [%4];"
                 : "=r"(r0), "=r"(r1), "=r"(r2), "=r"(r3) : "r"(a));
}
__device__ __forceinline__ void mma16816(float* d,
                                         u32 a0, u32 a1, u32 a2, u32 a3,
                                         u32 b0, u32 b1) {
    asm volatile("mma.sync.aligned.m16n8k16.row.col.f32.bf16.bf16.f32 "
                 "{%0,%1,%2,%3}, {%4,%5,%6,%7}, {%8,%9}, {%0,%1,%2,%3};"
                 : "+f"(d[0]), "+f"(d[1]), "+f"(d[2]), "+f"(d[3])
                 : "r"(a0), "r"(a1), "r"(a2), "r"(a3), "r"(b0), "r"(b1));
}

// ---------------------------------------------------------------------------
// Kernel 1: h = inp @ W  (fp32x2 GEMM); epilogue also emits bf16 hi/lo split
// ---------------------------------------------------------------------------
__global__ void __launch_bounds__(128) k_h_gemm(const float* __restrict__ inp,
                                               const float* __restrict__ W) {
    if (blockIdx.x == 0 && threadIdx.x < BATCH) g_s2max_enc[threadIdx.x] = 0u;

    __shared__ float Ws[32][128];
    __shared__ float Is[64][36];

    const int t  = threadIdx.x;
    const int tx = t & 15;
    const int ty = t >> 4;
    const int m0 = blockIdx.x * 64;

    u64 acc2[8][4];
#pragma unroll
    for (int r = 0; r < 8; ++r)
#pragma unroll
        for (int c = 0; c < 4; ++c) acc2[r][c] = 0ull;

    for (int kc = 0; kc < FIN; kc += 32) {
        __syncthreads();
#pragma unroll
        for (int r = 0; r < 8; ++r) {
            int v = t + 128 * r;
            int k = v >> 5, fq = v & 31;
            *(float4*)&Ws[k][fq * 4] =
                *(const float4*)&W[(size_t)(kc + k) * FOUT + fq * 4];
        }
#pragma unroll
        for (int r = 0; r < 4; ++r) {
            int v = t + 128 * r;
            int m = v >> 3, kq = v & 7;
            *(float4*)&Is[m][kq * 4] =
                *(const float4*)&inp[(size_t)(m0 + m) * FIN + kc + kq * 4];
        }
        __syncthreads();

#pragma unroll
        for (int k = 0; k < 32; ++k) {
            u64 wv2[4];
            {
                ulonglong2 w01 = *(const ulonglong2*)&Ws[k][tx * 4];
                ulonglong2 w23 = *(const ulonglong2*)&Ws[k][64 + tx * 4];
                wv2[0] = w01.x; wv2[1] = w01.y; wv2[2] = w23.x; wv2[3] = w23.y;
            }
            u64 iv2[8];
#pragma unroll
            for (int r = 0; r < 8; ++r) iv2[r] = bcast2(Is[ty * 8 + r][k]);
#pragma unroll
            for (int r = 0; r < 8; ++r)
#pragma unroll
                for (int c = 0; c < 4; ++c)
                    ffma2(acc2[r][c], iv2[r], wv2[c]);
        }
    }

#pragma unroll
    for (int r = 0; r < 8; ++r)
#pragma unroll
        for (int c = 0; c < 4; ++c) {
            int f = (c < 2) ? (tx * 4 + 2 * c) : (64 + tx * 4 + 2 * (c - 2));
            size_t idx = (size_t)(m0 + ty * 8 + r) * FOUT + f;
            float2 v = unpack2(acc2[r][c]);
            g_h[idx]     = v.x;
            g_h[idx + 1] = v.y;
            __nv_bfloat162 hx = __floats2bfloat162_rn(v.x, v.y);
            float2 hf = __bfloat1622float2(hx);
            __nv_bfloat162 lx = __floats2bfloat162_rn(v.x - hf.x, v.y - hf.y);
            *(__nv_bfloat162*)&g_h_hi[idx] = hx;
            *(__nv_bfloat162*)&g_h_lo[idx] = lx;
        }
}

// ---------------------------------------------------------------------------
// Kernel 1b: s1, s2, batchwise max(s2)
// ---------------------------------------------------------------------------
__global__ void __launch_bounds__(128) k_scores(const float* __restrict__ a) {
    const int row  = blockIdx.x * 4 + (threadIdx.x >> 5);
    const int lane = threadIdx.x & 31;
    const float* hr = g_h + (size_t)row * FOUT;
    float s1 = 0.f, s2 = 0.f;
#pragma unroll
    for (int k = 0; k < 4; ++k) {
        float hv = hr[lane + 32 * k];
        s1 = fmaf(hv, a[lane + 32 * k], s1);
        s2 = fmaf(hv, a[FOUT + lane + 32 * k], s2);
    }
#pragma unroll
    for (int off = 16; off; off >>= 1) {
        s1 += __shfl_xor_sync(0xffffffffu, s1, off);
        s2 += __shfl_xor_sync(0xffffffffu, s2, off);
    }
    if (lane == 0) {
        g_s1[row] = s1;
        g_s2[row] = s2;
        atomicMax(&g_s2max_enc[row / NN], enc_f(s2));
    }
}

// ---------------------------------------------------------------------------
// Kernel 2: static-shift masked softmax (scalar, streaming) +
//           P@h on tensor cores (mma.sync bf16, 3-term split) + ELU
// ---------------------------------------------------------------------------
struct AttnSmem {
    __nv_bfloat16 hh[BJ][HH_STRIDE];   // 17408 B
    __nv_bfloat16 hl[BJ][HH_STRIDE];   // 17408
    __nv_bfloat16 ph[BI][PH_STRIDE];   //  9216
    __nv_bfloat16 pl[BI][PH_STRIDE];   //  9216
    float adjb[2][BI][BJ];             // 32768
    float s2s[2][BJ];                  //   512
    float s1s[BI];                     //   256
    float bss[BI];                     //   256
    float l[BI];                       //   256
};

__global__ void __launch_bounds__(128, 2) k_attn(const float* __restrict__ adj,
                                                 float* __restrict__ out) {
    extern __shared__ char smc[];
    AttnSmem& s = *reinterpret_cast<AttnSmem*>(smc);

    const int b    = blockIdx.y;
    const int i0   = blockIdx.x * BI;
    const int t    = threadIdx.x;
    const int lane = t & 31;
    const int w    = t >> 5;        // warp 0..3

    // per-row constants into smem
    if (t < BI) {
        float s2max = dec_f(g_s2max_enc[b]);
        float s1v   = g_s1[(size_t)b * NN + i0 + t];
        s.s1s[t] = s1v;
        s.bss[t] = -fmaxf(0.0f, s1v + s2max) * LOG2E_F;
    }

    float D[16][4];
#pragma unroll
    for (int q = 0; q < 16; ++q)
#pragma unroll
        for (int e = 0; e < 4; ++e) D[q][e] = 0.0f;

    float rowsum[16];
#pragma unroll
    for (int rr = 0; rr < 16; ++rr) rowsum[rr] = 0.0f;

    const __nv_bfloat16* hhg = g_h_hi + (size_t)b * NN * FOUT;
    const __nv_bfloat16* hlg = g_h_lo + (size_t)b * NN * FOUT;
    const float*       arow0 = adj + ((size_t)b * NN + i0) * NN;

    const u32 hh_base = smem_u32(&s.hh[0][0]);
    const u32 hl_base = smem_u32(&s.hl[0][0]);
    const u32 ph_base = smem_u32(&s.ph[0][0]);
    const u32 pl_base = smem_u32(&s.pl[0][0]);

    // ldmatrix per-lane address components
    const u32 mlow = (lane >> 3) & 1;   // row +8 selector
    const u32 mhi  = lane >> 4;         // col +8 selector
    const u32 r8   = lane & 7;
    const u32 aoff = (u32)(w * 16 + mlow * 8 + r8) * (PH_STRIDE * 2) + mhi * 16;
    const u32 boff = (u32)(mlow * 8 + r8) * (HH_STRIDE * 2) + mhi * 16;

    // ---- prologue: prefetch adj chunk 0 + s2 slice 0 (group A0)
    {
#pragma unroll
        for (int r = 0; r < 8; ++r) {
            int v = t + 128 * r;
            int row = v >> 4, q = v & 15;
            cp16(smem_u32(&s.adjb[0][row][q * 4]), arow0 + (size_t)row * NN + q * 4);
        }
        if (t < BJ) cp4(smem_u32(&s.s2s[0][t]), &g_s2[(size_t)b * NN + t]);
        CP_COMMIT();
    }
    __syncthreads();   // s1s/bss visible

    for (int c = 0; c < NCHUNK; ++c) {
        const int jc  = c * BJ;
        const int buf = c & 1;

        __syncthreads();            // previous GEMM done with hh/hl

        // ---- stage h chunk (hi+lo) via cp.async (group H_c)
#pragma unroll
        for (int r = 0; r < 16; ++r) {
            int v   = t + 128 * r;            // 0..2047
            int arr = v >> 10;                // 0: hi, 1: lo
            int rem = v & 1023;
            int j   = rem >> 4, q = rem & 15; // 16B chunk q of row j
            size_t src = ((size_t)(jc + j)) * FOUT + q * 8;
            u32 dst = (arr ? hl_base : hh_base) + (u32)j * (HH_STRIDE * 2) + q * 16;
            cp16(dst, (arr ? hlg : hhg) + src);
        }
        CP_COMMIT();

        CP_WAIT1();                 // adj chunk c landed (h may fly)
        __syncthreads();

        // ---- streaming logit phase: warp w rows w*16..+15, lane -> j=2lane,+1
#pragma unroll
        for (int rr = 0; rr < 16; ++rr) {
            const int i = w * 16 + rr;
            const float2 av  = *(const float2*)&s.adjb[buf][i][lane * 2];
            const float2 s2v = *(const float2*)&s.s2s[buf][lane * 2];
            const float  s1v = s.s1s[i];
            const float  bs  = s.bss[i];

            float e0 = s1v + s2v.x,           e1 = s1v + s2v.y;
            float l0 = fmaxf(e0, ALPHA * e0), l1 = fmaxf(e1, ALPHA * e1);
            float r0 = (av.x > 0.0f) ? av.x * l0 : NEG_INFV;
            float r1 = (av.y > 0.0f) ? av.y * l1 : NEG_INFV;
            float p0 = fexp2n(fmaf(r0, LOG2E_F, bs));
            float p1 = fexp2n(fmaf(r1, LOG2E_F, bs));
            p0 = (av.x > 0.0f) ? p0 : 0.0f;
            p1 = (av.y > 0.0f) ? p1 : 0.0f;

            rowsum[rr] += p0 + p1;

            __nv_bfloat162 hx = __floats2bfloat162_rn(p0, p1);
            float2 hf = __bfloat1622float2(hx);
            __nv_bfloat162 lx = __floats2bfloat162_rn(p0 - hf.x, p1 - hf.y);
            *(__nv_bfloat162*)&s.ph[i][lane * 2] = hx;
            *(__nv_bfloat162*)&s.pl[i][lane * 2] = lx;
        }

        // ---- prefetch adj chunk c+1 (group A_{c+1}, overlaps GEMM)
        if (c + 1 < NCHUNK) {
            const int nb = buf ^ 1;
            const float* asrc = arow0 + jc + BJ;
#pragma unroll
            for (int r = 0; r < 8; ++r) {
                int v = t + 128 * r;
                int row = v >> 4, q = v & 15;
                cp16(smem_u32(&s.adjb[nb][row][q * 4]), asrc + (size_t)row * NN + q * 4);
            }
            if (t < BJ) cp4(smem_u32(&s.s2s[nb][t]),
                            &g_s2[(size_t)b * NN + jc + BJ + t]);
            CP_COMMIT();
        }

        CP_WAIT1();                 // h chunk c landed (adj c+1 may fly)
        __syncthreads();            // everyone's P + h visible

        // ---- tensor GEMM: D += P @ h  (64x64x128, bf16 3-term split)
#pragma unroll
        for (int ks = 0; ks < 4; ++ks) {
            u32 ah0, ah1, ah2, ah3, al0, al1, al2, al3;
            ldsm_x4 (ah0, ah1, ah2, ah3, ph_base + aoff + ks * 32);
            ldsm_x4 (al0, al1, al2, al3, pl_base + aoff + ks * 32);
            const u32 krow = (u32)ks * 16 * (HH_STRIDE * 2);
#pragma unroll
            for (int nt2 = 0; nt2 < 8; ++nt2) {
                u32 bh0, bh1, bh2, bh3, bl0, bl1, bl2, bl3;
                ldsm_x4t(bh0, bh1, bh2, bh3, hh_base + krow + nt2 * 32 + boff);
                ldsm_x4t(bl0, bl1, bl2, bl3, hl_base + krow + nt2 * 32 + boff);
                mma16816(D[nt2 * 2],     ah0, ah1, ah2, ah3, bh0, bh1);
                mma16816(D[nt2 * 2],     ah0, ah1, ah2, ah3, bl0, bl1);
                mma16816(D[nt2 * 2],     al0, al1, al2, al3, bh0, bh1);
                mma16816(D[nt2 * 2 + 1], ah0, ah1, ah2, ah3, bh2, bh3);
                mma16816(D[nt2 * 2 + 1], ah0, ah1, ah2, ah3, bl2, bl3);
                mma16816(D[nt2 * 2 + 1], al0, al1, al2, al3, bh2, bh3);
            }
        }
    }

    // ---- final row-sum reduction
#pragma unroll
    for (int rr = 0; rr < 16; ++rr) {
        float v = rowsum[rr];
#pragma unroll
        for (int off = 16; off; off >>= 1)
            v += __shfl_xor_sync(0xffffffffu, v, off);
        if (lane == 0) s.l[w * 16 + rr] = v;
    }
    __syncthreads();

    // ---- epilogue: normalize, ELU, write (m16n8 D-frag layout)
    {
        const int g   = lane >> 2;
        const int tig = lane & 3;
        const float li0 = 1.0f / s.l[w * 16 + g];
        const float li1 = 1.0f / s.l[w * 16 + g + 8];
        float* o0 = out + ((size_t)b * NN + i0 + w * 16 + g)     * FOUT;
        float* o1 = out + ((size_t)b * NN + i0 + w * 16 + g + 8) * FOUT;
#pragma unroll
        for (int tile = 0; tile < 16; ++tile) {
            const int col = tile * 8 + tig * 2;
            float v0 = D[tile][0] * li0, v1 = D[tile][1] * li0;
            float v2 = D[tile][2] * li1, v3 = D[tile][3] * li1;
            v0 = (v0 > 0.0f) ? v0 : expm1f(v0);
            v1 = (v1 > 0.0f) ? v1 : expm1f(v1);
            v2 = (v2 > 0.0f) ? v2 : expm1f(v2);
            v3 = (v3 > 0.0f) ? v3 : expm1f(v3);
            *(float2*)&o0[col] = make_float2(v0, v1);
            *(float2*)&o1[col] = make_float2(v2, v3);
        }
    }
}

// ---------------------------------------------------------------------------
extern "C" void kernel_launch(void* const* d_in, const int* in_sizes, int n_in,
                              void* d_out, int out_size) {
    const float* inp = (const float*)d_in[0];   // (4,4096,256)
    const float* adj = (const float*)d_in[1];   // (4,4096,4096)
    const float* W   = (const float*)d_in[2];   // (256,128)
    const float* a   = (const float*)d_in[3];   // (256,1)
    float* out = (float*)d_out;                 // (4,4096,128)

    (void)in_sizes; (void)n_in; (void)out_size;

    const int smem_bytes = (int)sizeof(AttnSmem);   // ~87 KB -> 2 CTAs/SM
    cudaFuncSetAttribute(k_attn, cudaFuncAttributeMaxDynamicSharedMemorySize,
                         smem_bytes);

    k_h_gemm<<<(BATCH * NN) / 64, 128>>>(inp, W);
    k_scores<<<(BATCH * NN) / 4, 128>>>(a);

    dim3 grid(NN / BI, BATCH);
    k_attn<<<grid, 128, smem_bytes>>>(adj, out);
}

// round 8
// speedup vs baseline: 3.3773x; 1.2237x over previous
#include <cuda_runtime.h>
#include <cuda_bf16.h>
#include <cuda_fp16.h>
#include <cstdint>
#include <math.h>

#define ALPHA    0.2f
#define NEG_INFV (-1000000000000.0f)
#define LOG2E_F  1.4426950408889634f

#define BATCH 4
#define NN    4096
#define FIN   256
#define FOUT  128

#define BI 64              // query rows per block
#define BJ 64              // key chunk
#define NCHUNK (NN / BJ)   // 64

#define PH_STRIDE 72       // fp16 per P row (144 B, 16B-aligned)
#define HH_STRIDE 136      // fp16 per h row (272 B, 16B-aligned)

typedef unsigned long long u64;
typedef unsigned int       u32;

// scratch (device globals: allocation-free)
__device__ float    g_h   [BATCH * NN * FOUT];
__device__ __half   g_h_hi[BATCH * NN * FOUT];
__device__ __half   g_h_lo[BATCH * NN * FOUT];
__device__ float    g_s1[BATCH * NN];
__device__ float    g_s2[BATCH * NN];
__device__ unsigned g_s2max_enc[BATCH];

// ---------------------------------------------------------------------------
// helpers
// ---------------------------------------------------------------------------
__device__ __forceinline__ unsigned enc_f(float f) {
    int i = __float_as_int(f);
    unsigned u = (unsigned)i;
    return (i < 0) ? ~u : (u | 0x80000000u);
}
__device__ __forceinline__ float dec_f(unsigned u) {
    int i = (u & 0x80000000u) ? (int)(u & 0x7fffffffu) : (int)~u;
    return __int_as_float(i);
}
__device__ __forceinline__ void ffma2(u64& d, u64 a, u64 b) {
    asm("fma.rn.f32x2 %0, %1, %2, %0;" : "+l"(d) : "l"(a), "l"(b));
}
__device__ __forceinline__ u64 bcast2(float x) {
    u64 r; asm("mov.b64 %0, {%1, %1};" : "=l"(r) : "f"(x)); return r;
}
__device__ __forceinline__ float2 unpack2(u64 v) {
    float2 f; asm("mov.b64 {%0, %1}, %2;" : "=f"(f.x), "=f"(f.y) : "l"(v)); return f;
}
__device__ __forceinline__ float fexp2n(float x) {   // 2^x, x <= 0, FMA-pipe only
    x = fmaxf(x, -126.0f);
    float z = x + 12582912.0f;
    int   n = __float_as_int(z) - 0x4B400000;
    float f = x - (z - 12582912.0f);
    float p = fmaf(0.0013333558f, f, 0.0096181291f);
    p = fmaf(p, f, 0.0555041087f);
    p = fmaf(p, f, 0.2402265070f);
    p = fmaf(p, f, 0.6931471806f);
    p = fmaf(p, f, 1.0f);
    return __int_as_float((n + 127) << 23) * p;
}
__device__ __forceinline__ u32 smem_u32(const void* p) {
    u32 a;
    asm("{ .reg .u64 t; cvta.to.shared.u64 t, %1; cvt.u32.u64 %0, t; }"
        : "=r"(a) : "l"(p));
    return a;
}
__device__ __forceinline__ void cp16(u32 dst, const void* src) {
    asm volatile("cp.async.cg.shared.global [%0], [%1], 16;"
                 :: "r"(dst), "l"(src) : "memory");
}
__device__ __forceinline__ void cp4(u32 dst, const void* src) {
    asm volatile("cp.async.ca.shared.global [%0], [%1], 4;"
                 :: "r"(dst), "l"(src) : "memory");
}
#define CP_COMMIT() asm volatile("cp.async.commit_group;" ::: "memory")
#define CP_WAIT1()  asm volatile("cp.async.wait_group 1;"  ::: "memory")

__device__ __forceinline__ void ldsm_x4(u32& r0, u32& r1, u32& r2, u32& r3, u32 a) {
    asm volatile("ldmatrix.sync.aligned.m8n8.x4.shared.b16 {%0,%1,%2,%3}, [%4];"
                 : "=r"(r0), "=r"(r1), "=r"(r2), "=r"(r3) : "r"(a));
}
__device__ __forceinline__ void ldsm_x4t(u32& r0, u32& r1, u32& r2, u32& r3, u32 a) {
    asm volatile("ldmatrix.sync.aligned.m8n8.x4.trans.shared.b16 {%0,%1,%2,%3}, [%4];"
                 : "=r"(r0), "=r"(r1), "=r"(r2), "=r"(r3) : "r"(a));
}
__device__ __forceinline__ void mma16816h(float* d,
                                          u32 a0, u32 a1, u32 a2, u32 a3,
                                          u32 b0, u32 b1) {
    asm volatile("mma.sync.aligned.m16n8k16.row.col.f32.f16.f16.f32 "
                 "{%0,%1,%2,%3}, {%4,%5,%6,%7}, {%8,%9}, {%0,%1,%2,%3};"
                 : "+f"(d[0]), "+f"(d[1]), "+f"(d[2]), "+f"(d[3])
                 : "r"(a0), "r"(a1), "r"(a2), "r"(a3), "r"(b0), "r"(b1));
}

// ---------------------------------------------------------------------------
// Kernel 1: h = inp @ W  (fp32x2 GEMM); epilogue emits fp16 hi/lo split of h
// ---------------------------------------------------------------------------
__global__ void __launch_bounds__(128) k_h_gemm(const float* __restrict__ inp,
                                               const float* __restrict__ W) {
    if (blockIdx.x == 0 && threadIdx.x < BATCH) g_s2max_enc[threadIdx.x] = 0u;

    __shared__ float Ws[32][128];
    __shared__ float Is[64][36];

    const int t  = threadIdx.x;
    const int tx = t & 15;
    const int ty = t >> 4;
    const int m0 = blockIdx.x * 64;

    u64 acc2[8][4];
#pragma unroll
    for (int r = 0; r < 8; ++r)
#pragma unroll
        for (int c = 0; c < 4; ++c) acc2[r][c] = 0ull;

    for (int kc = 0; kc < FIN; kc += 32) {
        __syncthreads();
#pragma unroll
        for (int r = 0; r < 8; ++r) {
            int v = t + 128 * r;
            int k = v >> 5, fq = v & 31;
            *(float4*)&Ws[k][fq * 4] =
                *(const float4*)&W[(size_t)(kc + k) * FOUT + fq * 4];
        }
#pragma unroll
        for (int r = 0; r < 4; ++r) {
            int v = t + 128 * r;
            int m = v >> 3, kq = v & 7;
            *(float4*)&Is[m][kq * 4] =
                *(const float4*)&inp[(size_t)(m0 + m) * FIN + kc + kq * 4];
        }
        __syncthreads();

#pragma unroll
        for (int k = 0; k < 32; ++k) {
            u64 wv2[4];
            {
                ulonglong2 w01 = *(const ulonglong2*)&Ws[k][tx * 4];
                ulonglong2 w23 = *(const ulonglong2*)&Ws[k][64 + tx * 4];
                wv2[0] = w01.x; wv2[1] = w01.y; wv2[2] = w23.x; wv2[3] = w23.y;
            }
            u64 iv2[8];
#pragma unroll
            for (int r = 0; r < 8; ++r) iv2[r] = bcast2(Is[ty * 8 + r][k]);
#pragma unroll
            for (int r = 0; r < 8; ++r)
#pragma unroll
                for (int c = 0; c < 4; ++c)
                    ffma2(acc2[r][c], iv2[r], wv2[c]);
        }
    }

#pragma unroll
    for (int r = 0; r < 8; ++r)
#pragma unroll
        for (int c = 0; c < 4; ++c) {
            int f = (c < 2) ? (tx * 4 + 2 * c) : (64 + tx * 4 + 2 * (c - 2));
            size_t idx = (size_t)(m0 + ty * 8 + r) * FOUT + f;
            float2 v = unpack2(acc2[r][c]);
            g_h[idx]     = v.x;
            g_h[idx + 1] = v.y;
            __half2 hx = __floats2half2_rn(v.x, v.y);
            float2  hf = __half22float2(hx);
            __half2 lx = __floats2half2_rn(v.x - hf.x, v.y - hf.y);
            *(__half2*)&g_h_hi[idx] = hx;
            *(__half2*)&g_h_lo[idx] = lx;
        }
}

// ---------------------------------------------------------------------------
// Kernel 1b: s1, s2, batchwise max(s2)
// ---------------------------------------------------------------------------
__global__ void __launch_bounds__(128) k_scores(const float* __restrict__ a) {
    const int row  = blockIdx.x * 4 + (threadIdx.x >> 5);
    const int lane = threadIdx.x & 31;
    const float* hr = g_h + (size_t)row * FOUT;
    float s1 = 0.f, s2 = 0.f;
#pragma unroll
    for (int k = 0; k < 4; ++k) {
        float hv = hr[lane + 32 * k];
        s1 = fmaf(hv, a[lane + 32 * k], s1);
        s2 = fmaf(hv, a[FOUT + lane + 32 * k], s2);
    }
#pragma unroll
    for (int off = 16; off; off >>= 1) {
        s1 += __shfl_xor_sync(0xffffffffu, s1, off);
        s2 += __shfl_xor_sync(0xffffffffu, s2, off);
    }
    if (lane == 0) {
        g_s1[row] = s1;
        g_s2[row] = s2;
        atomicMax(&g_s2max_enc[row / NN], enc_f(s2));
    }
}

// ---------------------------------------------------------------------------
// Kernel 2: static-shift masked softmax (scalar, streaming) +
//           P@h on tensor cores: 2-pass asymmetric fp16 (P fp16, h hi/lo)
// ---------------------------------------------------------------------------
struct AttnSmem {
    __half hh[BJ][HH_STRIDE];          // 17408 B
    __half hl[BJ][HH_STRIDE];          // 17408
    __half ph[BI][PH_STRIDE];          //  9216
    float adjb[2][BI][BJ];             // 32768
    float s2s[2][BJ];                  //   512
    float s1s[BI];                     //   256
    float bss[BI];                     //   256
    float l[BI];                       //   256
};

__global__ void __launch_bounds__(128, 2) k_attn(const float* __restrict__ adj,
                                                 float* __restrict__ out) {
    extern __shared__ char smc[];
    AttnSmem& s = *reinterpret_cast<AttnSmem*>(smc);

    const int b    = blockIdx.y;
    const int i0   = blockIdx.x * BI;
    const int t    = threadIdx.x;
    const int lane = t & 31;
    const int w    = t >> 5;        // warp 0..3

    if (t < BI) {
        float s2max = dec_f(g_s2max_enc[b]);
        float s1v   = g_s1[(size_t)b * NN + i0 + t];
        s.s1s[t] = s1v;
        s.bss[t] = -fmaxf(0.0f, s1v + s2max) * LOG2E_F;
    }

    float D[16][4];
#pragma unroll
    for (int q = 0; q < 16; ++q)
#pragma unroll
        for (int e = 0; e < 4; ++e) D[q][e] = 0.0f;

    float rowsum[16];
#pragma unroll
    for (int rr = 0; rr < 16; ++rr) rowsum[rr] = 0.0f;

    const __half* hhg = g_h_hi + (size_t)b * NN * FOUT;
    const __half* hlg = g_h_lo + (size_t)b * NN * FOUT;
    const float* arow0 = adj + ((size_t)b * NN + i0) * NN;

    const u32 hh_base = smem_u32(&s.hh[0][0]);
    const u32 hl_base = smem_u32(&s.hl[0][0]);
    const u32 ph_base = smem_u32(&s.ph[0][0]);

    // ldmatrix per-lane address components
    const u32 mlow = (lane >> 3) & 1;
    const u32 mhi  = lane >> 4;
    const u32 r8   = lane & 7;
    const u32 aoff = (u32)(w * 16 + mlow * 8 + r8) * (PH_STRIDE * 2) + mhi * 16;
    const u32 boff = (u32)(mlow * 8 + r8) * (HH_STRIDE * 2) + mhi * 16;

    // ---- prologue: prefetch adj chunk 0 + s2 slice 0
    {
#pragma unroll
        for (int r = 0; r < 8; ++r) {
            int v = t + 128 * r;
            int row = v >> 4, q = v & 15;
            cp16(smem_u32(&s.adjb[0][row][q * 4]), arow0 + (size_t)row * NN + q * 4);
        }
        if (t < BJ) cp4(smem_u32(&s.s2s[0][t]), &g_s2[(size_t)b * NN + t]);
        CP_COMMIT();
    }
    __syncthreads();

    for (int c = 0; c < NCHUNK; ++c) {
        const int jc  = c * BJ;
        const int buf = c & 1;

        __syncthreads();            // previous GEMM done with hh/hl

        // ---- stage h chunk (hi+lo fp16, 256 B/row = 16 x 16B chunks per row)
#pragma unroll
        for (int r = 0; r < 16; ++r) {
            int v   = t + 128 * r;            // 0..2047
            int arr = v >> 10;                // 0: hi, 1: lo
            int rem = v & 1023;
            int j   = rem >> 4, q = rem & 15; // 16B chunk q of row j
            size_t src = ((size_t)(jc + j)) * FOUT + q * 8;
            u32 dst = (arr ? hl_base : hh_base) + (u32)j * (HH_STRIDE * 2) + q * 16;
            cp16(dst, (arr ? hlg : hhg) + src);
        }
        CP_COMMIT();

        CP_WAIT1();                 // adj chunk c landed (h may fly)
        __syncthreads();

        // ---- streaming logit phase: warp w rows w*16..+15, lane -> j=2lane,+1
#pragma unroll
        for (int rr = 0; rr < 16; ++rr) {
            const int i = w * 16 + rr;
            const float2 av  = *(const float2*)&s.adjb[buf][i][lane * 2];
            const float2 s2v = *(const float2*)&s.s2s[buf][lane * 2];
            const float  s1v = s.s1s[i];
            const float  bs  = s.bss[i];

            float e0 = s1v + s2v.x,           e1 = s1v + s2v.y;
            float l0 = fmaxf(e0, ALPHA * e0), l1 = fmaxf(e1, ALPHA * e1);
            float r0 = (av.x > 0.0f) ? av.x * l0 : NEG_INFV;
            float r1 = (av.y > 0.0f) ? av.y * l1 : NEG_INFV;
            float p0 = fexp2n(fmaf(r0, LOG2E_F, bs));
            float p1 = fexp2n(fmaf(r1, LOG2E_F, bs));
            p0 = (av.x > 0.0f) ? p0 : 0.0f;
            p1 = (av.y > 0.0f) ? p1 : 0.0f;

            __half2 hx = __floats2half2_rn(p0, p1);
            float2  hf = __half22float2(hx);
            rowsum[rr] += hf.x + hf.y;        // denominator matches fp16 P
            *(__half2*)&s.ph[i][lane * 2] = hx;
        }

        // ---- prefetch adj chunk c+1 (overlaps GEMM)
        if (c + 1 < NCHUNK) {
            const int nb = buf ^ 1;
            const float* asrc = arow0 + jc + BJ;
#pragma unroll
            for (int r = 0; r < 8; ++r) {
                int v = t + 128 * r;
                int row = v >> 4, q = v & 15;
                cp16(smem_u32(&s.adjb[nb][row][q * 4]), asrc + (size_t)row * NN + q * 4);
            }
            if (t < BJ) cp4(smem_u32(&s.s2s[nb][t]),
                            &g_s2[(size_t)b * NN + jc + BJ + t]);
            CP_COMMIT();
        }

        CP_WAIT1();                 // h chunk c landed (adj c+1 may fly)
        __syncthreads();            // everyone's P + h visible

        // ---- tensor GEMM: D += P @ (Hh + Hl)  (64x64x128, fp16 2-pass)
#pragma unroll
        for (int ks = 0; ks < 4; ++ks) {
            u32 a0, a1, a2, a3;
            ldsm_x4(a0, a1, a2, a3, ph_base + aoff + ks * 32);
            const u32 krow = (u32)ks * 16 * (HH_STRIDE * 2);
#pragma unroll
            for (int nt2 = 0; nt2 < 8; ++nt2) {
                u32 bh0, bh1, bh2, bh3, bl0, bl1, bl2, bl3;
                ldsm_x4t(bh0, bh1, bh2, bh3, hh_base + krow + nt2 * 32 + boff);
                ldsm_x4t(bl0, bl1, bl2, bl3, hl_base + krow + nt2 * 32 + boff);
                mma16816h(D[nt2 * 2],     a0, a1, a2, a3, bh0, bh1);
                mma16816h(D[nt2 * 2],     a0, a1, a2, a3, bl0, bl1);
                mma16816h(D[nt2 * 2 + 1], a0, a1, a2, a3, bh2, bh3);
                mma16816h(D[nt2 * 2 + 1], a0, a1, a2, a3, bl2, bl3);
            }
        }
    }

    // ---- final row-sum reduction
#pragma unroll
    for (int rr = 0; rr < 16; ++rr) {
        float v = rowsum[rr];
#pragma unroll
        for (int off = 16; off; off >>= 1)
            v += __shfl_xor_sync(0xffffffffu, v, off);
        if (lane == 0) s.l[w * 16 + rr] = v;
    }
    __syncthreads();

    // ---- epilogue: normalize, ELU, write (m16n8 D-frag layout)
    {
        const int g   = lane >> 2;
        const int tig = lane & 3;
        const float li0 = 1.0f / s.l[w * 16 + g];
        const float li1 = 1.0f / s.l[w * 16 + g + 8];
        float* o0 = out + ((size_t)b * NN + i0 + w * 16 + g)     * FOUT;
        float* o1 = out + ((size_t)b * NN + i0 + w * 16 + g + 8) * FOUT;
#pragma unroll
        for (int tile = 0; tile < 16; ++tile) {
            const int col = tile * 8 + tig * 2;
            float v0 = D[tile][0] * li0, v1 = D[tile][1] * li0;
            float v2 = D[tile][2] * li1, v3 = D[tile][3] * li1;
            v0 = (v0 > 0.0f) ? v0 : expm1f(v0);
            v1 = (v1 > 0.0f) ? v1 : expm1f(v1);
            v2 = (v2 > 0.0f) ? v2 : expm1f(v2);
            v3 = (v3 > 0.0f) ? v3 : expm1f(v3);
            *(float2*)&o0[col] = make_float2(v0, v1);
            *(float2*)&o1[col] = make_float2(v2, v3);
        }
    }
}

// ---------------------------------------------------------------------------
extern "C" void kernel_launch(void* const* d_in, const int* in_sizes, int n_in,
                              void* d_out, int out_size) {
    const float* inp = (const float*)d_in[0];   // (4,4096,256)
    const float* adj = (const float*)d_in[1];   // (4,4096,4096)
    const float* W   = (const float*)d_in[2];   // (256,128)
    const float* a   = (const float*)d_in[3];   // (256,1)
    float* out = (float*)d_out;                 // (4,4096,128)

    (void)in_sizes; (void)n_in; (void)out_size;

    const int smem_bytes = (int)sizeof(AttnSmem);   // ~78 KB -> 2 CTAs/SM
    cudaFuncSetAttribute(k_attn, cudaFuncAttributeMaxDynamicSharedMemorySize,
                         smem_bytes);

    k_h_gemm<<<(BATCH * NN) / 64, 128>>>(inp, W);
    k_scores<<<(BATCH * NN) / 4, 128>>>(a);

    dim3 grid(NN / BI, BATCH);
    k_attn<<<grid, 128, smem_bytes>>>(adj, out);
}

// round 9
// speedup vs baseline: 4.2462x; 1.2573x over previous
#include <cuda_runtime.h>
#include <cuda_bf16.h>
#include <cuda_fp16.h>
#include <cstdint>
#include <math.h>

#define ALPHA    0.2f
#define NEG_INFV (-1000000000000.0f)
#define LOG2E_F  1.4426950408889634f

#define BATCH 4
#define NN    4096
#define FIN   256
#define FOUT  128

#define BI 64              // query rows per block
#define BJ 64              // key chunk
#define NCHUNK (NN / BJ)   // 64

#define PH_STRIDE 72       // fp16 per P row (144 B, 16B-aligned)
#define HH_STRIDE 136      // fp16 per h row (272 B, 16B-aligned)

typedef unsigned long long u64;
typedef unsigned int       u32;

// scratch (device globals: allocation-free)
__device__ float    g_h   [BATCH * NN * FOUT];
__device__ __half   g_h_hi[BATCH * NN * FOUT];
__device__ float    g_s1[BATCH * NN];
__device__ float    g_s2[BATCH * NN];
__device__ unsigned g_s2max_enc[BATCH];

// ---------------------------------------------------------------------------
// helpers
// ---------------------------------------------------------------------------
__device__ __forceinline__ unsigned enc_f(float f) {
    int i = __float_as_int(f);
    unsigned u = (unsigned)i;
    return (i < 0) ? ~u : (u | 0x80000000u);
}
__device__ __forceinline__ float dec_f(unsigned u) {
    int i = (u & 0x80000000u) ? (int)(u & 0x7fffffffu) : (int)~u;
    return __int_as_float(i);
}
__device__ __forceinline__ void ffma2(u64& d, u64 a, u64 b) {
    asm("fma.rn.f32x2 %0, %1, %2, %0;" : "+l"(d) : "l"(a), "l"(b));
}
__device__ __forceinline__ u64 bcast2(float x) {
    u64 r; asm("mov.b64 %0, {%1, %1};" : "=l"(r) : "f"(x)); return r;
}
__device__ __forceinline__ float2 unpack2(u64 v) {
    float2 f; asm("mov.b64 {%0, %1}, %2;" : "=f"(f.x), "=f"(f.y) : "l"(v)); return f;
}
__device__ __forceinline__ float fexp2n(float x) {   // 2^x, x <= 0, FMA-pipe only
    x = fmaxf(x, -126.0f);
    float z = x + 12582912.0f;
    int   n = __float_as_int(z) - 0x4B400000;
    float f = x - (z - 12582912.0f);
    float p = fmaf(0.0013333558f, f, 0.0096181291f);
    p = fmaf(p, f, 0.0555041087f);
    p = fmaf(p, f, 0.2402265070f);
    p = fmaf(p, f, 0.6931471806f);
    p = fmaf(p, f, 1.0f);
    return __int_as_float((n + 127) << 23) * p;
}
__device__ __forceinline__ u32 smem_u32(const void* p) {
    u32 a;
    asm("{ .reg .u64 t; cvta.to.shared.u64 t, %1; cvt.u32.u64 %0, t; }"
        : "=r"(a) : "l"(p));
    return a;
}
__device__ __forceinline__ void cp16(u32 dst, const void* src) {
    asm volatile("cp.async.cg.shared.global [%0], [%1], 16;"
                 :: "r"(dst), "l"(src) : "memory");
}
__device__ __forceinline__ void cp4(u32 dst, const void* src) {
    asm volatile("cp.async.ca.shared.global [%0], [%1], 4;"
                 :: "r"(dst), "l"(src) : "memory");
}
#define CP_COMMIT() asm volatile("cp.async.commit_group;" ::: "memory")
#define CP_WAIT1()  asm volatile("cp.async.wait_group 1;"  ::: "memory")

__device__ __forceinline__ void ldsm_x4(u32& r0, u32& r1, u32& r2, u32& r3, u32 a) {
    asm volatile("ldmatrix.sync.aligned.m8n8.x4.shared.b16 {%0,%1,%2,%3}, [%4];"
                 : "=r"(r0), "=r"(r1), "=r"(r2), "=r"(r3) : "r"(a));
}
__device__ __forceinline__ void ldsm_x4t(u32& r0, u32& r1, u32& r2, u32& r3, u32 a) {
    asm volatile("ldmatrix.sync.aligned.m8n8.x4.trans.shared.b16 {%0,%1,%2,%3}, [%4];"
                 : "=r"(r0), "=r"(r1), "=r"(r2), "=r"(r3) : "r"(a));
}
__device__ __forceinline__ void mma16816h(float* d,
                                          u32 a0, u32 a1, u32 a2, u32 a3,
                                          u32 b0, u32 b1) {
    asm volatile("mma.sync.aligned.m16n8k16.row.col.f32.f16.f16.f32 "
                 "{%0,%1,%2,%3}, {%4,%5,%6,%7}, {%8,%9}, {%0,%1,%2,%3};"
                 : "+f"(d[0]), "+f"(d[1]), "+f"(d[2]), "+f"(d[3])
                 : "r"(a0), "r"(a1), "r"(a2), "r"(a3), "r"(b0), "r"(b1));
}

// ---------------------------------------------------------------------------
// Kernel 1: h = inp @ W  (fp32x2 GEMM); epilogue emits fp16 h
// ---------------------------------------------------------------------------
__global__ void __launch_bounds__(128) k_h_gemm(const float* __restrict__ inp,
                                               const float* __restrict__ W) {
    if (blockIdx.x == 0 && threadIdx.x < BATCH) g_s2max_enc[threadIdx.x] = 0u;

    __shared__ float Ws[32][128];
    __shared__ float Is[64][36];

    const int t  = threadIdx.x;
    const int tx = t & 15;
    const int ty = t >> 4;
    const int m0 = blockIdx.x * 64;

    u64 acc2[8][4];
#pragma unroll
    for (int r = 0; r < 8; ++r)
#pragma unroll
        for (int c = 0; c < 4; ++c) acc2[r][c] = 0ull;

    for (int kc = 0; kc < FIN; kc += 32) {
        __syncthreads();
#pragma unroll
        for (int r = 0; r < 8; ++r) {
            int v = t + 128 * r;
            int k = v >> 5, fq = v & 31;
            *(float4*)&Ws[k][fq * 4] =
                *(const float4*)&W[(size_t)(kc + k) * FOUT + fq * 4];
        }
#pragma unroll
        for (int r = 0; r < 4; ++r) {
            int v = t + 128 * r;
            int m = v >> 3, kq = v & 7;
            *(float4*)&Is[m][kq * 4] =
                *(const float4*)&inp[(size_t)(m0 + m) * FIN + kc + kq * 4];
        }
        __syncthreads();

#pragma unroll
        for (int k = 0; k < 32; ++k) {
            u64 wv2[4];
            {
                ulonglong2 w01 = *(const ulonglong2*)&Ws[k][tx * 4];
                ulonglong2 w23 = *(const ulonglong2*)&Ws[k][64 + tx * 4];
                wv2[0] = w01.x; wv2[1] = w01.y; wv2[2] = w23.x; wv2[3] = w23.y;
            }
            u64 iv2[8];
#pragma unroll
            for (int r = 0; r < 8; ++r) iv2[r] = bcast2(Is[ty * 8 + r][k]);
#pragma unroll
            for (int r = 0; r < 8; ++r)
#pragma unroll
                for (int c = 0; c < 4; ++c)
                    ffma2(acc2[r][c], iv2[r], wv2[c]);
        }
    }

#pragma unroll
    for (int r = 0; r < 8; ++r)
#pragma unroll
        for (int c = 0; c < 4; ++c) {
            int f = (c < 2) ? (tx * 4 + 2 * c) : (64 + tx * 4 + 2 * (c - 2));
            size_t idx = (size_t)(m0 + ty * 8 + r) * FOUT + f;
            float2 v = unpack2(acc2[r][c]);
            g_h[idx]     = v.x;
            g_h[idx + 1] = v.y;
            *(__half2*)&g_h_hi[idx] = __floats2half2_rn(v.x, v.y);
        }
}

// ---------------------------------------------------------------------------
// Kernel 1b: s1, s2, batchwise max(s2)
// ---------------------------------------------------------------------------
__global__ void __launch_bounds__(128) k_scores(const float* __restrict__ a) {
    const int row  = blockIdx.x * 4 + (threadIdx.x >> 5);
    const int lane = threadIdx.x & 31;
    const float* hr = g_h + (size_t)row * FOUT;
    float s1 = 0.f, s2 = 0.f;
#pragma unroll
    for (int k = 0; k < 4; ++k) {
        float hv = hr[lane + 32 * k];
        s1 = fmaf(hv, a[lane + 32 * k], s1);
        s2 = fmaf(hv, a[FOUT + lane + 32 * k], s2);
    }
#pragma unroll
    for (int off = 16; off; off >>= 1) {
        s1 += __shfl_xor_sync(0xffffffffu, s1, off);
        s2 += __shfl_xor_sync(0xffffffffu, s2, off);
    }
    if (lane == 0) {
        g_s1[row] = s1;
        g_s2[row] = s2;
        atomicMax(&g_s2max_enc[row / NN], enc_f(s2));
    }
}

// ---------------------------------------------------------------------------
// Kernel 2: static-shift masked softmax (scalar, streaming) +
//           P@h on tensor cores: single-pass fp16
// ---------------------------------------------------------------------------
struct AttnSmem {
    __half hh[BJ][HH_STRIDE];          // 17408 B
    __half ph[BI][PH_STRIDE];          //  9216
    float adjb[2][BI][BJ];             // 32768
    float s2s[2][BJ];                  //   512
    float s1s[BI];                     //   256
    float bss[BI];                     //   256
    float l[BI];                       //   256
};

__global__ void __launch_bounds__(128, 2) k_attn(const float* __restrict__ adj,
                                                 float* __restrict__ out) {
    extern __shared__ char smc[];
    AttnSmem& s = *reinterpret_cast<AttnSmem*>(smc);

    const int b    = blockIdx.y;
    const int i0   = blockIdx.x * BI;
    const int t    = threadIdx.x;
    const int lane = t & 31;
    const int w    = t >> 5;        // warp 0..3

    if (t < BI) {
        float s2max = dec_f(g_s2max_enc[b]);
        float s1v   = g_s1[(size_t)b * NN + i0 + t];
        s.s1s[t] = s1v;
        s.bss[t] = -fmaxf(0.0f, s1v + s2max) * LOG2E_F;
    }

    float D[16][4];
#pragma unroll
    for (int q = 0; q < 16; ++q)
#pragma unroll
        for (int e = 0; e < 4; ++e) D[q][e] = 0.0f;

    float rowsum[16];
#pragma unroll
    for (int rr = 0; rr < 16; ++rr) rowsum[rr] = 0.0f;

    const __half* hhg  = g_h_hi + (size_t)b * NN * FOUT;
    const float* arow0 = adj + ((size_t)b * NN + i0) * NN;

    const u32 hh_base = smem_u32(&s.hh[0][0]);
    const u32 ph_base = smem_u32(&s.ph[0][0]);

    // ldmatrix per-lane address components
    const u32 mlow = (lane >> 3) & 1;
    const u32 mhi  = lane >> 4;
    const u32 r8   = lane & 7;
    const u32 aoff = (u32)(w * 16 + mlow * 8 + r8) * (PH_STRIDE * 2) + mhi * 16;
    const u32 boff = (u32)(mlow * 8 + r8) * (HH_STRIDE * 2) + mhi * 16;

    // ---- prologue: prefetch adj chunk 0 + s2 slice 0
    {
#pragma unroll
        for (int r = 0; r < 8; ++r) {
            int v = t + 128 * r;
            int row = v >> 4, q = v & 15;
            cp16(smem_u32(&s.adjb[0][row][q * 4]), arow0 + (size_t)row * NN + q * 4);
        }
        if (t < BJ) cp4(smem_u32(&s.s2s[0][t]), &g_s2[(size_t)b * NN + t]);
        CP_COMMIT();
    }
    __syncthreads();

    for (int c = 0; c < NCHUNK; ++c) {
        const int jc  = c * BJ;
        const int buf = c & 1;

        __syncthreads();            // previous GEMM done with hh

        // ---- stage h chunk (fp16, 256 B/row = 16 x 16B chunks, 64 rows)
#pragma unroll
        for (int r = 0; r < 8; ++r) {
            int v = t + 128 * r;              // 0..1023
            int j = v >> 4, q = v & 15;       // 16B chunk q of row j
            size_t src = ((size_t)(jc + j)) * FOUT + q * 8;
            cp16(hh_base + (u32)j * (HH_STRIDE * 2) + q * 16, hhg + src);
        }
        CP_COMMIT();

        CP_WAIT1();                 // adj chunk c landed (h may fly)
        __syncthreads();

        // ---- streaming logit phase: warp w rows w*16..+15, lane -> j=2lane,+1
#pragma unroll
        for (int rr = 0; rr < 16; ++rr) {
            const int i = w * 16 + rr;
            const float2 av  = *(const float2*)&s.adjb[buf][i][lane * 2];
            const float2 s2v = *(const float2*)&s.s2s[buf][lane * 2];
            const float  s1v = s.s1s[i];
            const float  bs  = s.bss[i];

            float e0 = s1v + s2v.x,           e1 = s1v + s2v.y;
            float l0 = fmaxf(e0, ALPHA * e0), l1 = fmaxf(e1, ALPHA * e1);
            float r0 = (av.x > 0.0f) ? av.x * l0 : NEG_INFV;
            float r1 = (av.y > 0.0f) ? av.y * l1 : NEG_INFV;
            float p0 = fexp2n(fmaf(r0, LOG2E_F, bs));
            float p1 = fexp2n(fmaf(r1, LOG2E_F, bs));
            p0 = (av.x > 0.0f) ? p0 : 0.0f;
            p1 = (av.y > 0.0f) ? p1 : 0.0f;

            __half2 hx = __floats2half2_rn(p0, p1);
            float2  hf = __half22float2(hx);
            rowsum[rr] += hf.x + hf.y;        // denominator matches fp16 P
            *(__half2*)&s.ph[i][lane * 2] = hx;
        }

        // ---- prefetch adj chunk c+1 (overlaps GEMM)
        if (c + 1 < NCHUNK) {
            const int nb = buf ^ 1;
            const float* asrc = arow0 + jc + BJ;
#pragma unroll
            for (int r = 0; r < 8; ++r) {
                int v = t + 128 * r;
                int row = v >> 4, q = v & 15;
                cp16(smem_u32(&s.adjb[nb][row][q * 4]), asrc + (size_t)row * NN + q * 4);
            }
            if (t < BJ) cp4(smem_u32(&s.s2s[nb][t]),
                            &g_s2[(size_t)b * NN + jc + BJ + t]);
            CP_COMMIT();
        }

        CP_WAIT1();                 // h chunk c landed (adj c+1 may fly)
        __syncthreads();            // everyone's P + h visible

        // ---- tensor GEMM: D += P @ H  (64x64x128, fp16 single pass)
#pragma unroll
        for (int ks = 0; ks < 4; ++ks) {
            u32 a0, a1, a2, a3;
            ldsm_x4(a0, a1, a2, a3, ph_base + aoff + ks * 32);
            const u32 krow = (u32)ks * 16 * (HH_STRIDE * 2);
#pragma unroll
            for (int nt2 = 0; nt2 < 8; ++nt2) {
                u32 b0, b1, b2, b3;
                ldsm_x4t(b0, b1, b2, b3, hh_base + krow + nt2 * 32 + boff);
                mma16816h(D[nt2 * 2],     a0, a1, a2, a3, b0, b1);
                mma16816h(D[nt2 * 2 + 1], a0, a1, a2, a3, b2, b3);
            }
        }
    }

    // ---- final row-sum reduction
#pragma unroll
    for (int rr = 0; rr < 16; ++rr) {
        float v = rowsum[rr];
#pragma unroll
        for (int off = 16; off; off >>= 1)
            v += __shfl_xor_sync(0xffffffffu, v, off);
        if (lane == 0) s.l[w * 16 + rr] = v;
    }
    __syncthreads();

    // ---- epilogue: normalize, ELU, write (m16n8 D-frag layout)
    {
        const int g   = lane >> 2;
        const int tig = lane & 3;
        const float li0 = 1.0f / s.l[w * 16 + g];
        const float li1 = 1.0f / s.l[w * 16 + g + 8];
        float* o0 = out + ((size_t)b * NN + i0 + w * 16 + g)     * FOUT;
        float* o1 = out + ((size_t)b * NN + i0 + w * 16 + g + 8) * FOUT;
#pragma unroll
        for (int tile = 0; tile < 16; ++tile) {
            const int col = tile * 8 + tig * 2;
            float v0 = D[tile][0] * li0, v1 = D[tile][1] * li0;
            float v2 = D[tile][2] * li1, v3 = D[tile][3] * li1;
            v0 = (v0 > 0.0f) ? v0 : expm1f(v0);
            v1 = (v1 > 0.0f) ? v1 : expm1f(v1);
            v2 = (v2 > 0.0f) ? v2 : expm1f(v2);
            v3 = (v3 > 0.0f) ? v3 : expm1f(v3);
            *(float2*)&o0[col] = make_float2(v0, v1);
            *(float2*)&o1[col] = make_float2(v2, v3);
        }
    }
}

// ---------------------------------------------------------------------------
extern "C" void kernel_launch(void* const* d_in, const int* in_sizes, int n_in,
                              void* d_out, int out_size) {
    const float* inp = (const float*)d_in[0];   // (4,4096,256)
    const float* adj = (const float*)d_in[1];   // (4,4096,4096)
    const float* W   = (const float*)d_in[2];   // (256,128)
    const float* a   = (const float*)d_in[3];   // (256,1)
    float* out = (float*)d_out;                 // (4,4096,128)

    (void)in_sizes; (void)n_in; (void)out_size;

    const int smem_bytes = (int)sizeof(AttnSmem);   // ~61 KB -> 2 CTAs/SM
    cudaFuncSetAttribute(k_attn, cudaFuncAttributeMaxDynamicSharedMemorySize,
                         smem_bytes);

    k_h_gemm<<<(BATCH * NN) / 64, 128>>>(inp, W);
    k_scores<<<(BATCH * NN) / 4, 128>>>(a);

    dim3 grid(NN / BI, BATCH);
    k_attn<<<grid, 128, smem_bytes>>>(adj, out);
}